// round 13
// baseline (speedup 1.0000x reference)
#include <cuda_runtime.h>

#define NPTS 65536
#define NS 16
#define NPAIR (NPTS*NS)
#define MF 1048576.0f
#define EPS 1e-5f

typedef unsigned long long ull;

__device__ __forceinline__ ull ffma2(ull a, ull b, ull c) {
    ull d; asm("fma.rn.f32x2 %0,%1,%2,%3;" : "=l"(d) : "l"(a), "l"(b), "l"(c)); return d;
}
__device__ __forceinline__ ull fmul2(ull a, ull b) {
    ull d; asm("mul.rn.f32x2 %0,%1,%2;" : "=l"(d) : "l"(a), "l"(b)); return d;
}
__device__ __forceinline__ ull fadd2(ull a, ull b) {
    ull d; asm("add.rn.f32x2 %0,%1,%2;" : "=l"(d) : "l"(a), "l"(b)); return d;
}
__device__ __forceinline__ ull pack2(float lo, float hi) {
    ull d; asm("mov.b64 %0,{%1,%2};" : "=l"(d) : "f"(lo), "f"(hi)); return d;
}
__device__ __forceinline__ void unpack2(ull v, float& lo, float& hi) {
    asm("mov.b64 {%0,%1},%2;" : "=f"(lo), "=f"(hi) : "l"(v));
}

// ---------------- scratch ----------------
__device__ float  g_xq[NPTS*64];
__device__ float  g_xk[NPTS*64];
__device__ float  g_xv[NPTS*64];
__device__ float4 g_pr1r[NPAIR];   // raw pr1 {v0,v1,v2,0} per pair (from k1)
__device__ float4 g_prh4[NPAIR];   // {h0,h1,h2,0} per pair (post BN+relu)
__device__ float  g_w1[NPAIR*8];
__device__ float  g_acc[152];      // [0..5]=P, [8..135]=W, [136..151]=U
#define ACC_P (g_acc)
#define ACC_W (g_acc + 8)
#define ACC_U (g_acc + 136)

// ---------------- K1: qkv GEMM (64 pts/block) + pr1 raw store + BN-P stats ----------------
__global__ void __launch_bounds__(256) k1(
                   const float* __restrict__ x, const float* __restrict__ p,
                   const int* __restrict__ idx,
                   const float* __restrict__ Wq, const float* __restrict__ bq,
                   const float* __restrict__ Wk, const float* __restrict__ bk,
                   const float* __restrict__ Wv, const float* __restrict__ bv,
                   const float* __restrict__ Wp1, const float* __restrict__ bp1)
{
    extern __shared__ float sm[];
    float4* ws4  = (float4*)sm;            // [64][48] float4
    float*  xs   = sm + 64*48*4;           // [64][68]
    float4* bsm4 = (float4*)(xs + 64*68);  // [48]
    int tid = threadIdx.x;
    int base = blockIdx.x * 64;

    for (int i = tid; i < 64*48; i += 256) {
        int k = i / 48, r = i - k*48;
        int seg = r >> 4, tx = r & 15;
        const float4* src = (seg == 0) ? (const float4*)Wq :
                            (seg == 1) ? (const float4*)Wk : (const float4*)Wv;
        ws4[i] = src[k*16 + tx];
    }
    {
        float4* xs4 = (float4*)xs;
        for (int i = tid; i < 64*16; i += 256) {
            int pt = i >> 4, kk = i & 15;
            xs4[pt*17 + kk] = ((const float4*)x)[(base + pt)*16 + kk];
        }
    }
    if (tid < 48) {
        int seg = tid >> 4, tx = tid & 15;
        const float4* src = (seg == 0) ? (const float4*)bq :
                            (seg == 1) ? (const float4*)bk : (const float4*)bv;
        bsm4[tid] = src[tx];
    }
    __syncthreads();

    int tx = tid & 15, ty = tid >> 4;
    ulonglong2 acc[3][4];
    #pragma unroll
    for (int s = 0; s < 3; s++) {
        ulonglong2 b = ((ulonglong2*)bsm4)[s*16 + tx];
        #pragma unroll
        for (int r = 0; r < 4; r++) acc[s][r] = b;
    }

    #pragma unroll 4
    for (int kq = 0; kq < 16; kq++) {
        float4 aq[4];
        #pragma unroll
        for (int r = 0; r < 4; r++) aq[r] = *(float4*)&xs[(ty*4 + r)*68 + kq*4];
        #pragma unroll
        for (int e = 0; e < 4; e++) {
            int k = kq*4 + e;
            ull ap[4];
            #pragma unroll
            for (int r = 0; r < 4; r++) {
                float av = ((float*)&aq[r])[e];
                ap[r] = pack2(av, av);
            }
            #pragma unroll
            for (int s = 0; s < 3; s++) {
                ulonglong2 w2 = *(ulonglong2*)&ws4[k*48 + s*16 + tx];
                #pragma unroll
                for (int r = 0; r < 4; r++) {
                    acc[s][r].x = ffma2(ap[r], w2.x, acc[s][r].x);
                    acc[s][r].y = ffma2(ap[r], w2.y, acc[s][r].y);
                }
            }
        }
    }

    #pragma unroll
    for (int r = 0; r < 4; r++) {
        int pt = base + ty*4 + r;
        ((ulonglong2*)&g_xq[pt*64])[tx] = acc[0][r];
        ((ulonglong2*)&g_xk[pt*64])[tx] = acc[1][r];
        ((ulonglong2*)&g_xv[pt*64])[tx] = acc[2][r];
    }

    // ---- pr1 raw compute + store + stats over this block's 1024 pairs ----
    float w00 = Wp1[0], w01 = Wp1[1], w02 = Wp1[2];
    float w10 = Wp1[3], w11 = Wp1[4], w12 = Wp1[5];
    float w20 = Wp1[6], w21 = Wp1[7], w22 = Wp1[8];
    float c0 = bp1[0], c1 = bp1[1], c2 = bp1[2];
    float s0=0,s1=0,s2=0,q0=0,q1=0,q2=0;
    for (int t = tid; t < 1024; t += 256) {
        int n = base + (t >> 4);
        int g = idx[n*NS + (t & 15)];
        float r0 = p[g*3+0] - p[n*3+0];
        float r1 = p[g*3+1] - p[n*3+1];
        float r2 = p[g*3+2] - p[n*3+2];
        float v0 = c0 + r0*w00 + r1*w10 + r2*w20;
        float v1 = c1 + r0*w01 + r1*w11 + r2*w21;
        float v2 = c2 + r0*w02 + r1*w12 + r2*w22;
        g_pr1r[base*NS + t] = make_float4(v0, v1, v2, 0.f);
        s0 += v0; s1 += v1; s2 += v2;
        q0 += v0*v0; q1 += v1*v1; q2 += v2*v2;
    }
    #pragma unroll
    for (int off = 16; off; off >>= 1) {
        s0 += __shfl_xor_sync(0xffffffffu, s0, off);
        s1 += __shfl_xor_sync(0xffffffffu, s1, off);
        s2 += __shfl_xor_sync(0xffffffffu, s2, off);
        q0 += __shfl_xor_sync(0xffffffffu, q0, off);
        q1 += __shfl_xor_sync(0xffffffffu, q1, off);
        q2 += __shfl_xor_sync(0xffffffffu, q2, off);
    }
    __syncthreads();
    float* red = sm;
    int lane = tid & 31, wrp = tid >> 5;
    if (lane == 0) {
        red[wrp*6+0] = s0; red[wrp*6+1] = s1; red[wrp*6+2] = s2;
        red[wrp*6+3] = q0; red[wrp*6+4] = q1; red[wrp*6+5] = q2;
    }
    __syncthreads();
    if (tid < 6) {
        float t2 = 0.f;
        #pragma unroll
        for (int w = 0; w < 8; w++) t2 += red[w*6 + tid];
        atomicAdd(&ACC_P[tid], t2);
    }
}

// ---------------- K2: streaming BN-P + w-channel BN stats (4-way batched) ----------------
__global__ void __launch_bounds__(256) k2(
                   const int* __restrict__ idx,
                   const float* __restrict__ gp, const float* __restrict__ bpbn,
                   const float* __restrict__ Wp2, const float* __restrict__ bp2)
{
    __shared__ float4 prh4[1024];
    __shared__ float  xqn[64*64];
    __shared__ int    goff[1024];
    __shared__ float  sred[1024];
    int tid = threadIdx.x;
    int pair0 = blockIdx.x * 1024;
    int pbase = pair0 >> 4;

    for (int i = tid; i < 1024; i += 256) goff[i] = idx[pair0 + i] << 4;
    for (int i = tid; i < 4096; i += 256) xqn[i] = -g_xq[pbase*64 + i];

    float scP[3], shP[3];
    #pragma unroll
    for (int c = 0; c < 3; c++) {
        float mean = ACC_P[c] / MF;
        float var  = ACC_P[3+c] / MF - mean*mean;
        float sc   = gp[c] * rsqrtf(var + EPS);
        scP[c] = sc;
        shP[c] = bpbn[c] - mean*sc;
    }
    __syncthreads();

    #pragma unroll
    for (int kk = 0; kk < 4; kk++) {
        int t = tid + kk*256;
        float4 v = __ldg(&g_pr1r[pair0 + t]);
        float h0 = fmaxf(v.x*scP[0] + shP[0], 0.f);
        float h1 = fmaxf(v.y*scP[1] + shP[1], 0.f);
        float h2 = fmaxf(v.z*scP[2] + shP[2], 0.f);
        float4 h = make_float4(h0, h1, h2, 0.f);
        prh4[t] = h;
        g_prh4[pair0 + t] = h;
    }
    __syncthreads();

    int cq = (tid & 15) * 4;
    int lof = tid & 15;
    float4 A0q = __ldg((const float4*)&Wp2[cq]);
    float4 A1q = __ldg((const float4*)&Wp2[64 + cq]);
    float4 A2q = __ldg((const float4*)&Wp2[128 + cq]);
    float4 Bq  = __ldg((const float4*)&bp2[cq]);
    ulonglong2 A0u = *(ulonglong2*)&A0q, A1u = *(ulonglong2*)&A1q;
    ulonglong2 A2u = *(ulonglong2*)&A2q, Bu  = *(ulonglong2*)&Bq;

    ull s_lo = 0, s_hi = 0, ss_lo = 0, ss_hi = 0;
    int pl = tid >> 4;
    #pragma unroll 1
    for (int k = 0; k < 64; k += 4) {
        int t0 = pl + 16*k;
        float4 xkq[4], h4[4];
        ulonglong2 xqu[4];
        #pragma unroll
        for (int e = 0; e < 4; e++) {
            int t = t0 + 16*e;
            xkq[e] = __ldg((const float4*)g_xk + goff[t] + lof);
            h4[e]  = prh4[t];
            xqu[e] = *(ulonglong2*)&xqn[(t >> 4)*64 + cq];
        }
        #pragma unroll
        for (int e = 0; e < 4; e++) {
            ull h0p = pack2(h4[e].x, h4[e].x), h1p = pack2(h4[e].y, h4[e].y), h2p = pack2(h4[e].z, h4[e].z);
            ulonglong2 xku = *(ulonglong2*)&xkq[e];
            ull t_lo = ffma2(h2p, A2u.x, ffma2(h1p, A1u.x, ffma2(h0p, A0u.x, Bu.x)));
            ull t_hi = ffma2(h2p, A2u.y, ffma2(h1p, A1u.y, ffma2(h0p, A0u.y, Bu.y)));
            ull w_lo = fadd2(xku.x, fadd2(xqu[e].x, t_lo));
            ull w_hi = fadd2(xku.y, fadd2(xqu[e].y, t_hi));
            s_lo = fadd2(s_lo, w_lo); s_hi = fadd2(s_hi, w_hi);
            ss_lo = ffma2(w_lo, w_lo, ss_lo); ss_hi = ffma2(w_hi, w_hi, ss_hi);
        }
    }

    float v[8];
    unpack2(s_lo, v[0], v[1]); unpack2(s_hi, v[2], v[3]);
    unpack2(ss_lo, v[4], v[5]); unpack2(ss_hi, v[6], v[7]);
    #pragma unroll
    for (int i = 0; i < 8; i++) v[i] += __shfl_xor_sync(0xffffffffu, v[i], 16);
    int lane = tid & 31, wrp = tid >> 5;
    if (lane < 16) {
        #pragma unroll
        for (int i = 0; i < 8; i++) sred[lane*64 + wrp*8 + i] = v[i];
    }
    __syncthreads();
    if (tid < 128) {
        int q = tid >> 3, vi = tid & 7;
        float s = 0.f;
        #pragma unroll
        for (int w = 0; w < 8; w++) s += sred[q*64 + w*8 + vi];
        int gi = (vi < 4) ? (q*4 + vi) : (64 + q*4 + vi - 4);
        atomicAdd(&ACC_W[gi], s);
    }
}

// ---------------- K3: 16 lanes/pair, reg tables, 2-way interleaved + goff ----------------
__global__ void __launch_bounds__(256, 2) k3(
                   const int* __restrict__ idx,
                   const float* __restrict__ Wp2, const float* __restrict__ bp2,
                   const float* __restrict__ gw1, const float* __restrict__ bw1bn,
                   const float* __restrict__ Ww1, const float* __restrict__ bw1)
{
    __shared__ float xqn[32*64];
    __shared__ int   gixs[512];
    __shared__ float sS[64];
    __shared__ float wred[8*16];
    int tid = threadIdx.x;
    int lane = tid & 31, wrp = tid >> 5;
    int pair0 = blockIdx.x * 512;
    int pbase = pair0 >> 4;
    int cq = (tid & 15) * 4;
    int lof = tid & 15;
    int slot = tid >> 4;
    int P = (lane >> 2) & 3;

    if (tid < 64) {
        int c = tid;
        float mean = ACC_W[c] / MF;
        float var  = ACC_W[64 + c] / MF - mean*mean;
        sS[c] = gw1[c] * rsqrtf(var + EPS);
    }
    for (int i = tid; i < 512; i += 256) gixs[i] = idx[pair0 + i] << 4;

    ull A0u[2], A1u[2], A2u[2], Bu[2], Su[2];
    {
        float a0[4], a1[4], a2[4], bb[4], sv[4];
        #pragma unroll
        for (int e = 0; e < 4; e++) {
            int c = cq + e;
            float mean = ACC_W[c] / MF;
            float var  = ACC_W[64 + c] / MF - mean*mean;
            float sc   = gw1[c] * rsqrtf(var + EPS);
            float sh   = bw1bn[c] - mean*sc;
            sv[e] = sc;
            a0[e] = Wp2[c]*sc; a1[e] = Wp2[64+c]*sc; a2[e] = Wp2[128+c]*sc;
            bb[e] = bp2[c]*sc + sh;
        }
        A0u[0] = pack2(a0[0], a0[1]); A0u[1] = pack2(a0[2], a0[3]);
        A1u[0] = pack2(a1[0], a1[1]); A1u[1] = pack2(a1[2], a1[3]);
        A2u[0] = pack2(a2[0], a2[1]); A2u[1] = pack2(a2[2], a2[3]);
        Bu[0]  = pack2(bb[0], bb[1]); Bu[1]  = pack2(bb[2], bb[3]);
        Su[0]  = pack2(sv[0], sv[1]); Su[1]  = pack2(sv[2], sv[3]);
    }

    ull Wr[4][4];
    #pragma unroll
    for (int e = 0; e < 4; e++)
        #pragma unroll
        for (int s = 0; s < 4; s++)
            Wr[e][s] = __ldg((const ull*)Ww1 + (cq + e)*4 + (P ^ s));
    ull biasu = __ldg((const ull*)bw1 + P);
    __syncthreads();

    for (int i = tid; i < 2048; i += 256)
        xqn[i] = -g_xq[(size_t)pbase*64 + i] * sS[i & 63];
    __syncthreads();

    const ulonglong2* xkb = (const ulonglong2*)g_xk;
    ull stS = 0, stQ = 0;

    #pragma unroll 1
    for (int k = 0; k < 32; k += 2) {
        int li0 = slot + (k << 4);
        int li1 = li0 + 16;
        int pr_0 = pair0 + li0, pr_1 = pair0 + li1;
        float4 hA = __ldg(&g_prh4[pr_0]);
        float4 hB = __ldg(&g_prh4[pr_1]);
        ulonglong2 xkA = __ldg(xkb + gixs[li0] + lof);
        ulonglong2 xkB = __ldg(xkb + gixs[li1] + lof);
        ulonglong2 xqA = *(const ulonglong2*)&xqn[(k << 6) + cq];
        ulonglong2 xqB = *(const ulonglong2*)&xqn[((k + 1) << 6) + cq];

        ull a0A, a1A, a2A, a3A;
        {
            ull h0p = pack2(hA.x, hA.x), h1p = pack2(hA.y, hA.y), h2p = pack2(hA.z, hA.z);
            ull r_lo = ffma2(h2p, A2u[0], ffma2(h1p, A1u[0], ffma2(h0p, A0u[0], Bu[0])));
            ull r_hi = ffma2(h2p, A2u[1], ffma2(h1p, A1u[1], ffma2(h0p, A0u[1], Bu[1])));
            ull w_lo = ffma2(xkA.x, Su[0], fadd2(xqA.x, r_lo));
            ull w_hi = ffma2(xkA.y, Su[1], fadd2(xqA.y, r_hi));
            float w0, w1, w2, w3;
            unpack2(w_lo, w0, w1); unpack2(w_hi, w2, w3);
            ull wp0 = pack2(fmaxf(w0,0.f), fmaxf(w0,0.f));
            ull wp1 = pack2(fmaxf(w1,0.f), fmaxf(w1,0.f));
            ull wp2_ = pack2(fmaxf(w2,0.f), fmaxf(w2,0.f));
            ull wp3 = pack2(fmaxf(w3,0.f), fmaxf(w3,0.f));
            a0A = fmul2(wp0, Wr[0][0]); a1A = fmul2(wp0, Wr[0][1]);
            a2A = fmul2(wp0, Wr[0][2]); a3A = fmul2(wp0, Wr[0][3]);
            a0A = ffma2(wp1, Wr[1][0], a0A); a1A = ffma2(wp1, Wr[1][1], a1A);
            a2A = ffma2(wp1, Wr[1][2], a2A); a3A = ffma2(wp1, Wr[1][3], a3A);
            a0A = ffma2(wp2_, Wr[2][0], a0A); a1A = ffma2(wp2_, Wr[2][1], a1A);
            a2A = ffma2(wp2_, Wr[2][2], a2A); a3A = ffma2(wp2_, Wr[2][3], a3A);
            a0A = ffma2(wp3, Wr[3][0], a0A); a1A = ffma2(wp3, Wr[3][1], a1A);
            a2A = ffma2(wp3, Wr[3][2], a2A); a3A = ffma2(wp3, Wr[3][3], a3A);
        }
        ull a0B, a1B, a2B, a3B;
        {
            ull h0p = pack2(hB.x, hB.x), h1p = pack2(hB.y, hB.y), h2p = pack2(hB.z, hB.z);
            ull r_lo = ffma2(h2p, A2u[0], ffma2(h1p, A1u[0], ffma2(h0p, A0u[0], Bu[0])));
            ull r_hi = ffma2(h2p, A2u[1], ffma2(h1p, A1u[1], ffma2(h0p, A0u[1], Bu[1])));
            ull w_lo = ffma2(xkB.x, Su[0], fadd2(xqB.x, r_lo));
            ull w_hi = ffma2(xkB.y, Su[1], fadd2(xqB.y, r_hi));
            float w0, w1, w2, w3;
            unpack2(w_lo, w0, w1); unpack2(w_hi, w2, w3);
            ull wp0 = pack2(fmaxf(w0,0.f), fmaxf(w0,0.f));
            ull wp1 = pack2(fmaxf(w1,0.f), fmaxf(w1,0.f));
            ull wp2_ = pack2(fmaxf(w2,0.f), fmaxf(w2,0.f));
            ull wp3 = pack2(fmaxf(w3,0.f), fmaxf(w3,0.f));
            a0B = fmul2(wp0, Wr[0][0]); a1B = fmul2(wp0, Wr[0][1]);
            a2B = fmul2(wp0, Wr[0][2]); a3B = fmul2(wp0, Wr[0][3]);
            a0B = ffma2(wp1, Wr[1][0], a0B); a1B = ffma2(wp1, Wr[1][1], a1B);
            a2B = ffma2(wp1, Wr[1][2], a2B); a3B = ffma2(wp1, Wr[1][3], a3B);
            a0B = ffma2(wp2_, Wr[2][0], a0B); a1B = ffma2(wp2_, Wr[2][1], a1B);
            a2B = ffma2(wp2_, Wr[2][2], a2B); a3B = ffma2(wp2_, Wr[2][3], a3B);
            a0B = ffma2(wp3, Wr[3][0], a0B); a1B = ffma2(wp3, Wr[3][1], a1B);
            a2B = ffma2(wp3, Wr[3][2], a2B); a3B = ffma2(wp3, Wr[3][3], a3B);
        }

        ull tA2 = __shfl_xor_sync(0xffffffffu, a2A, 8);
        ull tB2 = __shfl_xor_sync(0xffffffffu, a2B, 8);
        ull tA3 = __shfl_xor_sync(0xffffffffu, a3A, 8);
        ull tB3 = __shfl_xor_sync(0xffffffffu, a3B, 8);
        a0A = fadd2(a0A, tA2); a0B = fadd2(a0B, tB2);
        a1A = fadd2(a1A, tA3); a1B = fadd2(a1B, tB3);
        ull uA = __shfl_xor_sync(0xffffffffu, a1A, 4);
        ull uB = __shfl_xor_sync(0xffffffffu, a1B, 4);
        a0A = fadd2(a0A, uA); a0B = fadd2(a0B, uB);
        uA = __shfl_xor_sync(0xffffffffu, a0A, 2);
        uB = __shfl_xor_sync(0xffffffffu, a0B, 2);
        a0A = fadd2(a0A, uA); a0B = fadd2(a0B, uB);
        uA = __shfl_xor_sync(0xffffffffu, a0A, 1);
        uB = __shfl_xor_sync(0xffffffffu, a0B, 1);
        a0A = fadd2(fadd2(a0A, uA), biasu);
        a0B = fadd2(fadd2(a0B, uB), biasu);

        if ((lane & 3) == 0) {
            *((ull*)g_w1 + (size_t)pr_0*4 + P) = a0A;
            *((ull*)g_w1 + (size_t)pr_1*4 + P) = a0B;
        }

        stS = fadd2(stS, fadd2(a0A, a0B));
        stQ = ffma2(a0A, a0A, stQ);
        stQ = ffma2(a0B, a0B, stQ);
    }

    stS = fadd2(stS, __shfl_xor_sync(0xffffffffu, stS, 16));
    stQ = fadd2(stQ, __shfl_xor_sync(0xffffffffu, stQ, 16));
    if (lane < 16 && (lane & 3) == 0) {
        float s0, s1, q0, q1;
        unpack2(stS, s0, s1); unpack2(stQ, q0, q1);
        wred[wrp*16 + 2*P]     = s0;
        wred[wrp*16 + 2*P + 1] = s1;
        wred[wrp*16 + 8 + 2*P]     = q0;
        wred[wrp*16 + 8 + 2*P + 1] = q1;
    }
    __syncthreads();
    if (tid < 16) {
        float s = 0.f;
        #pragma unroll
        for (int w = 0; w < 8; w++) s += wred[w*16 + tid];
        atomicAdd(&ACC_U[tid], s);
    }
}

// ---------------- K4: fused bn2+relu -> @Ww2 (transposed logits) -> softmax -> aggregate ----------------
__global__ void __launch_bounds__(256) k4(
                   const int* __restrict__ idx,
                   const float* __restrict__ Wp2, const float* __restrict__ bp2,
                   const float* __restrict__ gw2, const float* __restrict__ bw2bn,
                   const float* __restrict__ Ww2, const float* __restrict__ bw2,
                   float* __restrict__ out)
{
    __shared__ float  hs[4][128];
    __shared__ float  w2t[4][128];   // transposed: [t*16 + j]
    __shared__ float4 prs4[4][16];   // packed {h0,h1,h2,0} per neighbor
    __shared__ int    gix4[4][16];   // g*64
    __shared__ float  wp2s[192], bp2s[64], wws[64], bws[8];
    int tid = threadIdx.x;
    int sub = tid >> 6, ct = tid & 63;
    int n = blockIdx.x*4 + sub;

    for (int i = tid; i < 192; i += 256) wp2s[i] = Wp2[i];
    if (tid < 64) { bp2s[tid] = bp2[tid]; wws[tid] = Ww2[tid]; }
    if (tid < 8)  bws[tid] = bw2[tid];

    int u = ct & 7;
    float mean = ACC_U[u] / MF;
    float var  = ACC_U[8 + u] / MF - mean*mean;
    float sc2  = gw2[u] * rsqrtf(var + EPS);
    float sh2  = bw2bn[u] - mean*sc2;

    hs[sub][ct]      = fmaxf(g_w1[n*128 + ct]*sc2 + sh2, 0.f);
    hs[sub][ct + 64] = fmaxf(g_w1[n*128 + ct + 64]*sc2 + sh2, 0.f);
    if (ct < 16) {
        gix4[sub][ct] = idx[n*16 + ct] << 6;
        prs4[sub][ct] = g_prh4[n*16 + ct];
    }
    __syncthreads();

    // w2 logits, written transposed: [t][j]
    #pragma unroll
    for (int o = ct; o < 128; o += 64) {
        int j = o >> 3, t = o & 7;
        float v = bws[t];
        #pragma unroll
        for (int uu = 0; uu < 8; uu++) v += hs[sub][j*8 + uu] * wws[uu*8 + t];
        w2t[sub][t*16 + j] = v;
    }
    __syncthreads();

    // softmax: thread t owns contiguous row w2t[t*16 .. t*16+15]
    if (ct < 8) {
        float4* row = (float4*)&w2t[sub][ct*16];
        float4 r0 = row[0], r1 = row[1], r2 = row[2], r3 = row[3];
        float vv[16] = {r0.x,r0.y,r0.z,r0.w, r1.x,r1.y,r1.z,r1.w,
                        r2.x,r2.y,r2.z,r2.w, r3.x,r3.y,r3.z,r3.w};
        float m = -1e30f;
        #pragma unroll
        for (int j = 0; j < 16; j++) m = fmaxf(m, vv[j]);
        float ssum = 0.f;
        #pragma unroll
        for (int j = 0; j < 16; j++) { vv[j] = __expf(vv[j] - m); ssum += vv[j]; }
        float inv = 1.f / ssum;
        #pragma unroll
        for (int j = 0; j < 16; j++) vv[j] *= inv;
        row[0] = make_float4(vv[0], vv[1], vv[2], vv[3]);
        row[1] = make_float4(vv[4], vv[5], vv[6], vv[7]);
        row[2] = make_float4(vv[8], vv[9], vv[10], vv[11]);
        row[3] = make_float4(vv[12], vv[13], vv[14], vv[15]);
    }
    __syncthreads();

    // aggregate: hoist 16 softmax weights into registers, 1 LDS.128/j for pr
    int t = ct & 7;
    float a0 = wp2s[ct], a1 = wp2s[64 + ct], a2 = wp2s[128 + ct], bb = bp2s[ct];
    const float4* wrow = (const float4*)&w2t[sub][t*16];
    float4 W0 = wrow[0], W1 = wrow[1], W2 = wrow[2], W3 = wrow[3];
    float wreg[16] = {W0.x,W0.y,W0.z,W0.w, W1.x,W1.y,W1.z,W1.w,
                      W2.x,W2.y,W2.z,W2.w, W3.x,W3.y,W3.z,W3.w};
    float acc = 0.f;
    #pragma unroll
    for (int j = 0; j < 16; j++) {
        float v = __ldg(&g_xv[gix4[sub][j] + ct]);
        float4 h = prs4[sub][j];
        float pr = fmaf(h.z, a2, fmaf(h.y, a1, fmaf(h.x, a0, bb)));
        acc = fmaf(v + pr, wreg[j], acc);
    }
    out[n*64 + ct] = acc;
}

// ---------------- launch ----------------
extern "C" void kernel_launch(void* const* d_in, const int* in_sizes, int n_in,
                              void* d_out, int out_size)
{
    const float* p    = (const float*)d_in[0];
    const float* x    = (const float*)d_in[1];
    const int*   idx  = (const int*)d_in[2];
    const float* Wq   = (const float*)d_in[3];
    const float* bq   = (const float*)d_in[4];
    const float* Wk   = (const float*)d_in[5];
    const float* bk   = (const float*)d_in[6];
    const float* Wv   = (const float*)d_in[7];
    const float* bv   = (const float*)d_in[8];
    const float* Wp1  = (const float*)d_in[9];
    const float* bp1  = (const float*)d_in[10];
    const float* gp   = (const float*)d_in[11];
    const float* bpbn = (const float*)d_in[12];
    const float* Wp2  = (const float*)d_in[13];
    const float* bp2  = (const float*)d_in[14];
    const float* gw1  = (const float*)d_in[15];
    const float* bw1bn= (const float*)d_in[16];
    const float* Ww1  = (const float*)d_in[17];
    const float* bw1  = (const float*)d_in[18];
    const float* gw2  = (const float*)d_in[19];
    const float* bw2bn= (const float*)d_in[20];
    const float* Ww2  = (const float*)d_in[21];
    const float* bw2  = (const float*)d_in[22];
    float* out = (float*)d_out;

    size_t smem1 = (size_t)(64*48*4 + 64*68 + 48*4) * 4;  // ~66KB
    cudaFuncSetAttribute(k1, cudaFuncAttributeMaxDynamicSharedMemorySize, (int)smem1);

    void* accPtr = nullptr;
    cudaGetSymbolAddress(&accPtr, g_acc);
    cudaMemsetAsync(accPtr, 0, 152 * sizeof(float));

    k1<<<1024, 256, smem1>>>(x, p, idx, Wq, bq, Wk, bk, Wv, bv, Wp1, bp1);
    k2<<<1024, 256>>>(idx, gp, bpbn, Wp2, bp2);
    k3<<<2048, 256>>>(idx, Wp2, bp2, gw1, bw1bn, Ww1, bw1);
    k4<<<16384, 256>>>(idx, Wp2, bp2, gw2, bw2bn, Ww2, bw2, out);
}

// round 14
// speedup vs baseline: 1.0446x; 1.0446x over previous
#include <cuda_runtime.h>

#define NPTS 65536
#define NS 16
#define NPAIR (NPTS*NS)
#define MF 1048576.0f
#define EPS 1e-5f

typedef unsigned long long ull;

__device__ __forceinline__ ull ffma2(ull a, ull b, ull c) {
    ull d; asm("fma.rn.f32x2 %0,%1,%2,%3;" : "=l"(d) : "l"(a), "l"(b), "l"(c)); return d;
}
__device__ __forceinline__ ull fmul2(ull a, ull b) {
    ull d; asm("mul.rn.f32x2 %0,%1,%2;" : "=l"(d) : "l"(a), "l"(b)); return d;
}
__device__ __forceinline__ ull fadd2(ull a, ull b) {
    ull d; asm("add.rn.f32x2 %0,%1,%2;" : "=l"(d) : "l"(a), "l"(b)); return d;
}
__device__ __forceinline__ ull pack2(float lo, float hi) {
    ull d; asm("mov.b64 %0,{%1,%2};" : "=l"(d) : "f"(lo), "f"(hi)); return d;
}
__device__ __forceinline__ void unpack2(ull v, float& lo, float& hi) {
    asm("mov.b64 {%0,%1},%2;" : "=f"(lo), "=f"(hi) : "l"(v));
}

// ---------------- scratch ----------------
__device__ float  g_xq[NPTS*64];
__device__ float  g_xk[NPTS*64];
__device__ float  g_xv[NPTS*64];
__device__ float4 g_pr1r[NPAIR];   // raw pr1 {v0,v1,v2,0} per pair (from k1)
__device__ float4 g_prh4[NPAIR];   // {h0,h1,h2,0} per pair (post BN+relu)
__device__ float  g_w1[NPAIR*8];
__device__ float  g_acc[152];      // [0..5]=P, [8..135]=W, [136..151]=U
#define ACC_P (g_acc)
#define ACC_W (g_acc + 8)
#define ACC_U (g_acc + 136)

// ---------------- K1: qkv GEMM (64 pts/block) + pr1 raw store + BN-P stats ----------------
__global__ void __launch_bounds__(256) k1(
                   const float* __restrict__ x, const float* __restrict__ p,
                   const int* __restrict__ idx,
                   const float* __restrict__ Wq, const float* __restrict__ bq,
                   const float* __restrict__ Wk, const float* __restrict__ bk,
                   const float* __restrict__ Wv, const float* __restrict__ bv,
                   const float* __restrict__ Wp1, const float* __restrict__ bp1)
{
    extern __shared__ float sm[];
    float4* ws4  = (float4*)sm;            // [64][48] float4
    float*  xs   = sm + 64*48*4;           // [64][68]
    float4* bsm4 = (float4*)(xs + 64*68);  // [48]
    int tid = threadIdx.x;
    int base = blockIdx.x * 64;

    for (int i = tid; i < 64*48; i += 256) {
        int k = i / 48, r = i - k*48;
        int seg = r >> 4, tx = r & 15;
        const float4* src = (seg == 0) ? (const float4*)Wq :
                            (seg == 1) ? (const float4*)Wk : (const float4*)Wv;
        ws4[i] = src[k*16 + tx];
    }
    {
        float4* xs4 = (float4*)xs;
        for (int i = tid; i < 64*16; i += 256) {
            int pt = i >> 4, kk = i & 15;
            xs4[pt*17 + kk] = ((const float4*)x)[(base + pt)*16 + kk];
        }
    }
    if (tid < 48) {
        int seg = tid >> 4, tx = tid & 15;
        const float4* src = (seg == 0) ? (const float4*)bq :
                            (seg == 1) ? (const float4*)bk : (const float4*)bv;
        bsm4[tid] = src[tx];
    }
    __syncthreads();

    int tx = tid & 15, ty = tid >> 4;
    ulonglong2 acc[3][4];
    #pragma unroll
    for (int s = 0; s < 3; s++) {
        ulonglong2 b = ((ulonglong2*)bsm4)[s*16 + tx];
        #pragma unroll
        for (int r = 0; r < 4; r++) acc[s][r] = b;
    }

    #pragma unroll 4
    for (int kq = 0; kq < 16; kq++) {
        float4 aq[4];
        #pragma unroll
        for (int r = 0; r < 4; r++) aq[r] = *(float4*)&xs[(ty*4 + r)*68 + kq*4];
        #pragma unroll
        for (int e = 0; e < 4; e++) {
            int k = kq*4 + e;
            ull ap[4];
            #pragma unroll
            for (int r = 0; r < 4; r++) {
                float av = ((float*)&aq[r])[e];
                ap[r] = pack2(av, av);
            }
            #pragma unroll
            for (int s = 0; s < 3; s++) {
                ulonglong2 w2 = *(ulonglong2*)&ws4[k*48 + s*16 + tx];
                #pragma unroll
                for (int r = 0; r < 4; r++) {
                    acc[s][r].x = ffma2(ap[r], w2.x, acc[s][r].x);
                    acc[s][r].y = ffma2(ap[r], w2.y, acc[s][r].y);
                }
            }
        }
    }

    #pragma unroll
    for (int r = 0; r < 4; r++) {
        int pt = base + ty*4 + r;
        ((ulonglong2*)&g_xq[pt*64])[tx] = acc[0][r];
        ((ulonglong2*)&g_xk[pt*64])[tx] = acc[1][r];
        ((ulonglong2*)&g_xv[pt*64])[tx] = acc[2][r];
    }

    // ---- pr1 raw compute + store + stats over this block's 1024 pairs ----
    float w00 = Wp1[0], w01 = Wp1[1], w02 = Wp1[2];
    float w10 = Wp1[3], w11 = Wp1[4], w12 = Wp1[5];
    float w20 = Wp1[6], w21 = Wp1[7], w22 = Wp1[8];
    float c0 = bp1[0], c1 = bp1[1], c2 = bp1[2];
    float s0=0,s1=0,s2=0,q0=0,q1=0,q2=0;
    for (int t = tid; t < 1024; t += 256) {
        int n = base + (t >> 4);
        int g = idx[n*NS + (t & 15)];
        float r0 = p[g*3+0] - p[n*3+0];
        float r1 = p[g*3+1] - p[n*3+1];
        float r2 = p[g*3+2] - p[n*3+2];
        float v0 = c0 + r0*w00 + r1*w10 + r2*w20;
        float v1 = c1 + r0*w01 + r1*w11 + r2*w21;
        float v2 = c2 + r0*w02 + r1*w12 + r2*w22;
        g_pr1r[base*NS + t] = make_float4(v0, v1, v2, 0.f);
        s0 += v0; s1 += v1; s2 += v2;
        q0 += v0*v0; q1 += v1*v1; q2 += v2*v2;
    }
    #pragma unroll
    for (int off = 16; off; off >>= 1) {
        s0 += __shfl_xor_sync(0xffffffffu, s0, off);
        s1 += __shfl_xor_sync(0xffffffffu, s1, off);
        s2 += __shfl_xor_sync(0xffffffffu, s2, off);
        q0 += __shfl_xor_sync(0xffffffffu, q0, off);
        q1 += __shfl_xor_sync(0xffffffffu, q1, off);
        q2 += __shfl_xor_sync(0xffffffffu, q2, off);
    }
    __syncthreads();
    float* red = sm;
    int lane = tid & 31, wrp = tid >> 5;
    if (lane == 0) {
        red[wrp*6+0] = s0; red[wrp*6+1] = s1; red[wrp*6+2] = s2;
        red[wrp*6+3] = q0; red[wrp*6+4] = q1; red[wrp*6+5] = q2;
    }
    __syncthreads();
    if (tid < 6) {
        float t2 = 0.f;
        #pragma unroll
        for (int w = 0; w < 8; w++) t2 += red[w*6 + tid];
        atomicAdd(&ACC_P[tid], t2);
    }
}

// ---------------- K2: streaming BN-P + w-channel BN stats (4-way batched) ----------------
__global__ void __launch_bounds__(256) k2(
                   const int* __restrict__ idx,
                   const float* __restrict__ gp, const float* __restrict__ bpbn,
                   const float* __restrict__ Wp2, const float* __restrict__ bp2)
{
    __shared__ float4 prh4[1024];
    __shared__ float  xqn[64*64];
    __shared__ int    goff[1024];
    __shared__ float  sred[1024];
    int tid = threadIdx.x;
    int pair0 = blockIdx.x * 1024;
    int pbase = pair0 >> 4;

    for (int i = tid; i < 1024; i += 256) goff[i] = idx[pair0 + i] << 4;
    for (int i = tid; i < 4096; i += 256) xqn[i] = -g_xq[pbase*64 + i];

    float scP[3], shP[3];
    #pragma unroll
    for (int c = 0; c < 3; c++) {
        float mean = ACC_P[c] / MF;
        float var  = ACC_P[3+c] / MF - mean*mean;
        float sc   = gp[c] * rsqrtf(var + EPS);
        scP[c] = sc;
        shP[c] = bpbn[c] - mean*sc;
    }
    __syncthreads();

    #pragma unroll
    for (int kk = 0; kk < 4; kk++) {
        int t = tid + kk*256;
        float4 v = __ldg(&g_pr1r[pair0 + t]);
        float h0 = fmaxf(v.x*scP[0] + shP[0], 0.f);
        float h1 = fmaxf(v.y*scP[1] + shP[1], 0.f);
        float h2 = fmaxf(v.z*scP[2] + shP[2], 0.f);
        float4 h = make_float4(h0, h1, h2, 0.f);
        prh4[t] = h;
        g_prh4[pair0 + t] = h;
    }
    __syncthreads();

    int cq = (tid & 15) * 4;
    int lof = tid & 15;
    float4 A0q = __ldg((const float4*)&Wp2[cq]);
    float4 A1q = __ldg((const float4*)&Wp2[64 + cq]);
    float4 A2q = __ldg((const float4*)&Wp2[128 + cq]);
    float4 Bq  = __ldg((const float4*)&bp2[cq]);
    ulonglong2 A0u = *(ulonglong2*)&A0q, A1u = *(ulonglong2*)&A1q;
    ulonglong2 A2u = *(ulonglong2*)&A2q, Bu  = *(ulonglong2*)&Bq;

    ull s_lo = 0, s_hi = 0, ss_lo = 0, ss_hi = 0;
    int pl = tid >> 4;
    #pragma unroll 1
    for (int k = 0; k < 64; k += 4) {
        int t0 = pl + 16*k;
        float4 xkq[4], h4[4];
        ulonglong2 xqu[4];
        #pragma unroll
        for (int e = 0; e < 4; e++) {
            int t = t0 + 16*e;
            xkq[e] = __ldg((const float4*)g_xk + goff[t] + lof);
            h4[e]  = prh4[t];
            xqu[e] = *(ulonglong2*)&xqn[(t >> 4)*64 + cq];
        }
        #pragma unroll
        for (int e = 0; e < 4; e++) {
            ull h0p = pack2(h4[e].x, h4[e].x), h1p = pack2(h4[e].y, h4[e].y), h2p = pack2(h4[e].z, h4[e].z);
            ulonglong2 xku = *(ulonglong2*)&xkq[e];
            ull t_lo = ffma2(h2p, A2u.x, ffma2(h1p, A1u.x, ffma2(h0p, A0u.x, Bu.x)));
            ull t_hi = ffma2(h2p, A2u.y, ffma2(h1p, A1u.y, ffma2(h0p, A0u.y, Bu.y)));
            ull w_lo = fadd2(xku.x, fadd2(xqu[e].x, t_lo));
            ull w_hi = fadd2(xku.y, fadd2(xqu[e].y, t_hi));
            s_lo = fadd2(s_lo, w_lo); s_hi = fadd2(s_hi, w_hi);
            ss_lo = ffma2(w_lo, w_lo, ss_lo); ss_hi = ffma2(w_hi, w_hi, ss_hi);
        }
    }

    float v[8];
    unpack2(s_lo, v[0], v[1]); unpack2(s_hi, v[2], v[3]);
    unpack2(ss_lo, v[4], v[5]); unpack2(ss_hi, v[6], v[7]);
    #pragma unroll
    for (int i = 0; i < 8; i++) v[i] += __shfl_xor_sync(0xffffffffu, v[i], 16);
    int lane = tid & 31, wrp = tid >> 5;
    if (lane < 16) {
        #pragma unroll
        for (int i = 0; i < 8; i++) sred[lane*64 + wrp*8 + i] = v[i];
    }
    __syncthreads();
    if (tid < 128) {
        int q = tid >> 3, vi = tid & 7;
        float s = 0.f;
        #pragma unroll
        for (int w = 0; w < 8; w++) s += sred[q*64 + w*8 + vi];
        int gi = (vi < 4) ? (q*4 + vi) : (64 + q*4 + vi - 4);
        atomicAdd(&ACC_W[gi], s);
    }
}

// ---------------- K3: 16 lanes/pair, reg tables, 2-way interleaved + goff ----------------
__global__ void __launch_bounds__(256, 2) k3(
                   const int* __restrict__ idx,
                   const float* __restrict__ Wp2, const float* __restrict__ bp2,
                   const float* __restrict__ gw1, const float* __restrict__ bw1bn,
                   const float* __restrict__ Ww1, const float* __restrict__ bw1)
{
    __shared__ float xqn[32*64];
    __shared__ int   gixs[512];
    __shared__ float sS[64];
    __shared__ float wred[8*16];
    int tid = threadIdx.x;
    int lane = tid & 31, wrp = tid >> 5;
    int pair0 = blockIdx.x * 512;
    int pbase = pair0 >> 4;
    int cq = (tid & 15) * 4;
    int lof = tid & 15;
    int slot = tid >> 4;
    int P = (lane >> 2) & 3;

    if (tid < 64) {
        int c = tid;
        float mean = ACC_W[c] / MF;
        float var  = ACC_W[64 + c] / MF - mean*mean;
        sS[c] = gw1[c] * rsqrtf(var + EPS);
    }
    for (int i = tid; i < 512; i += 256) gixs[i] = idx[pair0 + i] << 4;

    ull A0u[2], A1u[2], A2u[2], Bu[2], Su[2];
    {
        float a0[4], a1[4], a2[4], bb[4], sv[4];
        #pragma unroll
        for (int e = 0; e < 4; e++) {
            int c = cq + e;
            float mean = ACC_W[c] / MF;
            float var  = ACC_W[64 + c] / MF - mean*mean;
            float sc   = gw1[c] * rsqrtf(var + EPS);
            float sh   = bw1bn[c] - mean*sc;
            sv[e] = sc;
            a0[e] = Wp2[c]*sc; a1[e] = Wp2[64+c]*sc; a2[e] = Wp2[128+c]*sc;
            bb[e] = bp2[c]*sc + sh;
        }
        A0u[0] = pack2(a0[0], a0[1]); A0u[1] = pack2(a0[2], a0[3]);
        A1u[0] = pack2(a1[0], a1[1]); A1u[1] = pack2(a1[2], a1[3]);
        A2u[0] = pack2(a2[0], a2[1]); A2u[1] = pack2(a2[2], a2[3]);
        Bu[0]  = pack2(bb[0], bb[1]); Bu[1]  = pack2(bb[2], bb[3]);
        Su[0]  = pack2(sv[0], sv[1]); Su[1]  = pack2(sv[2], sv[3]);
    }

    ull Wr[4][4];
    #pragma unroll
    for (int e = 0; e < 4; e++)
        #pragma unroll
        for (int s = 0; s < 4; s++)
            Wr[e][s] = __ldg((const ull*)Ww1 + (cq + e)*4 + (P ^ s));
    ull biasu = __ldg((const ull*)bw1 + P);
    __syncthreads();

    for (int i = tid; i < 2048; i += 256)
        xqn[i] = -g_xq[(size_t)pbase*64 + i] * sS[i & 63];
    __syncthreads();

    const ulonglong2* xkb = (const ulonglong2*)g_xk;
    ull stS = 0, stQ = 0;

    #pragma unroll 1
    for (int k = 0; k < 32; k += 2) {
        int li0 = slot + (k << 4);
        int li1 = li0 + 16;
        int pr_0 = pair0 + li0, pr_1 = pair0 + li1;
        float4 hA = __ldg(&g_prh4[pr_0]);
        float4 hB = __ldg(&g_prh4[pr_1]);
        ulonglong2 xkA = __ldg(xkb + gixs[li0] + lof);
        ulonglong2 xkB = __ldg(xkb + gixs[li1] + lof);
        ulonglong2 xqA = *(const ulonglong2*)&xqn[(k << 6) + cq];
        ulonglong2 xqB = *(const ulonglong2*)&xqn[((k + 1) << 6) + cq];

        ull a0A, a1A, a2A, a3A;
        {
            ull h0p = pack2(hA.x, hA.x), h1p = pack2(hA.y, hA.y), h2p = pack2(hA.z, hA.z);
            ull r_lo = ffma2(h2p, A2u[0], ffma2(h1p, A1u[0], ffma2(h0p, A0u[0], Bu[0])));
            ull r_hi = ffma2(h2p, A2u[1], ffma2(h1p, A1u[1], ffma2(h0p, A0u[1], Bu[1])));
            ull w_lo = ffma2(xkA.x, Su[0], fadd2(xqA.x, r_lo));
            ull w_hi = ffma2(xkA.y, Su[1], fadd2(xqA.y, r_hi));
            float w0, w1, w2, w3;
            unpack2(w_lo, w0, w1); unpack2(w_hi, w2, w3);
            ull wp0 = pack2(fmaxf(w0,0.f), fmaxf(w0,0.f));
            ull wp1 = pack2(fmaxf(w1,0.f), fmaxf(w1,0.f));
            ull wp2_ = pack2(fmaxf(w2,0.f), fmaxf(w2,0.f));
            ull wp3 = pack2(fmaxf(w3,0.f), fmaxf(w3,0.f));
            a0A = fmul2(wp0, Wr[0][0]); a1A = fmul2(wp0, Wr[0][1]);
            a2A = fmul2(wp0, Wr[0][2]); a3A = fmul2(wp0, Wr[0][3]);
            a0A = ffma2(wp1, Wr[1][0], a0A); a1A = ffma2(wp1, Wr[1][1], a1A);
            a2A = ffma2(wp1, Wr[1][2], a2A); a3A = ffma2(wp1, Wr[1][3], a3A);
            a0A = ffma2(wp2_, Wr[2][0], a0A); a1A = ffma2(wp2_, Wr[2][1], a1A);
            a2A = ffma2(wp2_, Wr[2][2], a2A); a3A = ffma2(wp2_, Wr[2][3], a3A);
            a0A = ffma2(wp3, Wr[3][0], a0A); a1A = ffma2(wp3, Wr[3][1], a1A);
            a2A = ffma2(wp3, Wr[3][2], a2A); a3A = ffma2(wp3, Wr[3][3], a3A);
        }
        ull a0B, a1B, a2B, a3B;
        {
            ull h0p = pack2(hB.x, hB.x), h1p = pack2(hB.y, hB.y), h2p = pack2(hB.z, hB.z);
            ull r_lo = ffma2(h2p, A2u[0], ffma2(h1p, A1u[0], ffma2(h0p, A0u[0], Bu[0])));
            ull r_hi = ffma2(h2p, A2u[1], ffma2(h1p, A1u[1], ffma2(h0p, A0u[1], Bu[1])));
            ull w_lo = ffma2(xkB.x, Su[0], fadd2(xqB.x, r_lo));
            ull w_hi = ffma2(xkB.y, Su[1], fadd2(xqB.y, r_hi));
            float w0, w1, w2, w3;
            unpack2(w_lo, w0, w1); unpack2(w_hi, w2, w3);
            ull wp0 = pack2(fmaxf(w0,0.f), fmaxf(w0,0.f));
            ull wp1 = pack2(fmaxf(w1,0.f), fmaxf(w1,0.f));
            ull wp2_ = pack2(fmaxf(w2,0.f), fmaxf(w2,0.f));
            ull wp3 = pack2(fmaxf(w3,0.f), fmaxf(w3,0.f));
            a0B = fmul2(wp0, Wr[0][0]); a1B = fmul2(wp0, Wr[0][1]);
            a2B = fmul2(wp0, Wr[0][2]); a3B = fmul2(wp0, Wr[0][3]);
            a0B = ffma2(wp1, Wr[1][0], a0B); a1B = ffma2(wp1, Wr[1][1], a1B);
            a2B = ffma2(wp1, Wr[1][2], a2B); a3B = ffma2(wp1, Wr[1][3], a3B);
            a0B = ffma2(wp2_, Wr[2][0], a0B); a1B = ffma2(wp2_, Wr[2][1], a1B);
            a2B = ffma2(wp2_, Wr[2][2], a2B); a3B = ffma2(wp2_, Wr[2][3], a3B);
            a0B = ffma2(wp3, Wr[3][0], a0B); a1B = ffma2(wp3, Wr[3][1], a1B);
            a2B = ffma2(wp3, Wr[3][2], a2B); a3B = ffma2(wp3, Wr[3][3], a3B);
        }

        ull tA2 = __shfl_xor_sync(0xffffffffu, a2A, 8);
        ull tB2 = __shfl_xor_sync(0xffffffffu, a2B, 8);
        ull tA3 = __shfl_xor_sync(0xffffffffu, a3A, 8);
        ull tB3 = __shfl_xor_sync(0xffffffffu, a3B, 8);
        a0A = fadd2(a0A, tA2); a0B = fadd2(a0B, tB2);
        a1A = fadd2(a1A, tA3); a1B = fadd2(a1B, tB3);
        ull uA = __shfl_xor_sync(0xffffffffu, a1A, 4);
        ull uB = __shfl_xor_sync(0xffffffffu, a1B, 4);
        a0A = fadd2(a0A, uA); a0B = fadd2(a0B, uB);
        uA = __shfl_xor_sync(0xffffffffu, a0A, 2);
        uB = __shfl_xor_sync(0xffffffffu, a0B, 2);
        a0A = fadd2(a0A, uA); a0B = fadd2(a0B, uB);
        uA = __shfl_xor_sync(0xffffffffu, a0A, 1);
        uB = __shfl_xor_sync(0xffffffffu, a0B, 1);
        a0A = fadd2(fadd2(a0A, uA), biasu);
        a0B = fadd2(fadd2(a0B, uB), biasu);

        if ((lane & 3) == 0) {
            *((ull*)g_w1 + (size_t)pr_0*4 + P) = a0A;
            *((ull*)g_w1 + (size_t)pr_1*4 + P) = a0B;
        }

        stS = fadd2(stS, fadd2(a0A, a0B));
        stQ = ffma2(a0A, a0A, stQ);
        stQ = ffma2(a0B, a0B, stQ);
    }

    stS = fadd2(stS, __shfl_xor_sync(0xffffffffu, stS, 16));
    stQ = fadd2(stQ, __shfl_xor_sync(0xffffffffu, stQ, 16));
    if (lane < 16 && (lane & 3) == 0) {
        float s0, s1, q0, q1;
        unpack2(stS, s0, s1); unpack2(stQ, q0, q1);
        wred[wrp*16 + 2*P]     = s0;
        wred[wrp*16 + 2*P + 1] = s1;
        wred[wrp*16 + 8 + 2*P]     = q0;
        wred[wrp*16 + 8 + 2*P + 1] = q1;
    }
    __syncthreads();
    if (tid < 16) {
        float s = 0.f;
        #pragma unroll
        for (int w = 0; w < 8; w++) s += wred[w*16 + tid];
        atomicAdd(&ACC_U[tid], s);
    }
}

// ---------------- K4: fused bn2+relu -> @Ww2 -> softmax -> aggregate (packed prs) ----------------
__global__ void __launch_bounds__(256) k4(
                   const int* __restrict__ idx,
                   const float* __restrict__ Wp2, const float* __restrict__ bp2,
                   const float* __restrict__ gw2, const float* __restrict__ bw2bn,
                   const float* __restrict__ Ww2, const float* __restrict__ bw2,
                   float* __restrict__ out)
{
    __shared__ float  hs[4][128];
    __shared__ float  w2s[4][128];   // [j*8 + t] (broadcast-friendly)
    __shared__ float4 prs4[4][16];   // packed {h0,h1,h2,0} per neighbor
    __shared__ int    gix4[4][16];   // g*64
    __shared__ float  wp2s[192], bp2s[64], wws[64], bws[8];
    int tid = threadIdx.x;
    int sub = tid >> 6, ct = tid & 63;
    int n = blockIdx.x*4 + sub;

    for (int i = tid; i < 192; i += 256) wp2s[i] = Wp2[i];
    if (tid < 64) { bp2s[tid] = bp2[tid]; wws[tid] = Ww2[tid]; }
    if (tid < 8)  bws[tid] = bw2[tid];

    int u = ct & 7;
    float mean = ACC_U[u] / MF;
    float var  = ACC_U[8 + u] / MF - mean*mean;
    float sc2  = gw2[u] * rsqrtf(var + EPS);
    float sh2  = bw2bn[u] - mean*sc2;

    hs[sub][ct]      = fmaxf(g_w1[n*128 + ct]*sc2 + sh2, 0.f);
    hs[sub][ct + 64] = fmaxf(g_w1[n*128 + ct + 64]*sc2 + sh2, 0.f);
    if (ct < 16) {
        gix4[sub][ct] = idx[n*16 + ct] << 6;
        prs4[sub][ct] = g_prh4[n*16 + ct];
    }
    __syncthreads();

    #pragma unroll
    for (int o = ct; o < 128; o += 64) {
        int j = o >> 3, t = o & 7;
        float v = bws[t];
        #pragma unroll
        for (int uu = 0; uu < 8; uu++) v += hs[sub][j*8 + uu] * wws[uu*8 + t];
        w2s[sub][o] = v;
    }
    __syncthreads();

    if (ct < 8) {
        int t = ct;
        float m = -1e30f;
        #pragma unroll
        for (int j = 0; j < 16; j++) m = fmaxf(m, w2s[sub][j*8 + t]);
        float e[16], ssum = 0.f;
        #pragma unroll
        for (int j = 0; j < 16; j++) { e[j] = __expf(w2s[sub][j*8 + t] - m); ssum += e[j]; }
        float inv = 1.f / ssum;
        #pragma unroll
        for (int j = 0; j < 16; j++) w2s[sub][j*8 + t] = e[j] * inv;
    }
    __syncthreads();

    int t = ct & 7;
    float a0 = wp2s[ct], a1 = wp2s[64 + ct], a2 = wp2s[128 + ct], bb = bp2s[ct];
    float acc = 0.f;
    #pragma unroll
    for (int j = 0; j < 16; j++) {
        float v = __ldg(&g_xv[gix4[sub][j] + ct]);
        float4 h = prs4[sub][j];
        float pr = fmaf(h.z, a2, fmaf(h.y, a1, fmaf(h.x, a0, bb)));
        acc = fmaf(v + pr, w2s[sub][j*8 + t], acc);
    }
    out[n*64 + ct] = acc;
}

// ---------------- launch ----------------
extern "C" void kernel_launch(void* const* d_in, const int* in_sizes, int n_in,
                              void* d_out, int out_size)
{
    const float* p    = (const float*)d_in[0];
    const float* x    = (const float*)d_in[1];
    const int*   idx  = (const int*)d_in[2];
    const float* Wq   = (const float*)d_in[3];
    const float* bq   = (const float*)d_in[4];
    const float* Wk   = (const float*)d_in[5];
    const float* bk   = (const float*)d_in[6];
    const float* Wv   = (const float*)d_in[7];
    const float* bv   = (const float*)d_in[8];
    const float* Wp1  = (const float*)d_in[9];
    const float* bp1  = (const float*)d_in[10];
    const float* gp   = (const float*)d_in[11];
    const float* bpbn = (const float*)d_in[12];
    const float* Wp2  = (const float*)d_in[13];
    const float* bp2  = (const float*)d_in[14];
    const float* gw1  = (const float*)d_in[15];
    const float* bw1bn= (const float*)d_in[16];
    const float* Ww1  = (const float*)d_in[17];
    const float* bw1  = (const float*)d_in[18];
    const float* gw2  = (const float*)d_in[19];
    const float* bw2bn= (const float*)d_in[20];
    const float* Ww2  = (const float*)d_in[21];
    const float* bw2  = (const float*)d_in[22];
    float* out = (float*)d_out;

    size_t smem1 = (size_t)(64*48*4 + 64*68 + 48*4) * 4;  // ~66KB
    cudaFuncSetAttribute(k1, cudaFuncAttributeMaxDynamicSharedMemorySize, (int)smem1);

    void* accPtr = nullptr;
    cudaGetSymbolAddress(&accPtr, g_acc);
    cudaMemsetAsync(accPtr, 0, 152 * sizeof(float));

    k1<<<1024, 256, smem1>>>(x, p, idx, Wq, bq, Wk, bk, Wv, bv, Wp1, bp1);
    k2<<<1024, 256>>>(idx, gp, bpbn, Wp2, bp2);
    k3<<<2048, 256>>>(idx, Wp2, bp2, gw1, bw1bn, Ww1, bw1);
    k4<<<16384, 256>>>(idx, Wp2, bp2, gw2, bw2bn, Ww2, bw2, out);
}

// round 15
// speedup vs baseline: 1.0517x; 1.0068x over previous
#include <cuda_runtime.h>

#define NPTS 65536
#define NS 16
#define NPAIR (NPTS*NS)
#define MF 1048576.0f
#define EPS 1e-5f

typedef unsigned long long ull;

__device__ __forceinline__ ull ffma2(ull a, ull b, ull c) {
    ull d; asm("fma.rn.f32x2 %0,%1,%2,%3;" : "=l"(d) : "l"(a), "l"(b), "l"(c)); return d;
}
__device__ __forceinline__ ull fmul2(ull a, ull b) {
    ull d; asm("mul.rn.f32x2 %0,%1,%2;" : "=l"(d) : "l"(a), "l"(b)); return d;
}
__device__ __forceinline__ ull fadd2(ull a, ull b) {
    ull d; asm("add.rn.f32x2 %0,%1,%2;" : "=l"(d) : "l"(a), "l"(b)); return d;
}
__device__ __forceinline__ ull pack2(float lo, float hi) {
    ull d; asm("mov.b64 %0,{%1,%2};" : "=l"(d) : "f"(lo), "f"(hi)); return d;
}
__device__ __forceinline__ void unpack2(ull v, float& lo, float& hi) {
    asm("mov.b64 {%0,%1},%2;" : "=f"(lo), "=f"(hi) : "l"(v));
}

// ---------------- scratch ----------------
__device__ float  g_xq[NPTS*64];
__device__ float  g_xk[NPTS*64];
__device__ float  g_xv[NPTS*64];
__device__ float4 g_pr1r[NPAIR];   // raw pr1 {v0,v1,v2,0} per pair (from k1)
__device__ float4 g_prh4[NPAIR];   // {h0,h1,h2,0} per pair (post BN+relu)
__device__ float  g_w1[NPAIR*8];
__device__ float  g_acc[152];      // [0..5]=P, [8..135]=W, [136..151]=U
#define ACC_P (g_acc)
#define ACC_W (g_acc + 8)
#define ACC_U (g_acc + 136)

// ---------------- K1: qkv GEMM (64 pts/block) + pr1 raw store + BN-P stats ----------------
__global__ void __launch_bounds__(256) k1(
                   const float* __restrict__ x, const float* __restrict__ p,
                   const int* __restrict__ idx,
                   const float* __restrict__ Wq, const float* __restrict__ bq,
                   const float* __restrict__ Wk, const float* __restrict__ bk,
                   const float* __restrict__ Wv, const float* __restrict__ bv,
                   const float* __restrict__ Wp1, const float* __restrict__ bp1)
{
    extern __shared__ float sm[];
    float4* ws4  = (float4*)sm;            // [64][48] float4
    float*  xs   = sm + 64*48*4;           // [64][68]
    float4* bsm4 = (float4*)(xs + 64*68);  // [48]
    int tid = threadIdx.x;
    int base = blockIdx.x * 64;

    for (int i = tid; i < 64*48; i += 256) {
        int k = i / 48, r = i - k*48;
        int seg = r >> 4, tx = r & 15;
        const float4* src = (seg == 0) ? (const float4*)Wq :
                            (seg == 1) ? (const float4*)Wk : (const float4*)Wv;
        ws4[i] = src[k*16 + tx];
    }
    {
        float4* xs4 = (float4*)xs;
        for (int i = tid; i < 64*16; i += 256) {
            int pt = i >> 4, kk = i & 15;
            xs4[pt*17 + kk] = ((const float4*)x)[(base + pt)*16 + kk];
        }
    }
    if (tid < 48) {
        int seg = tid >> 4, tx = tid & 15;
        const float4* src = (seg == 0) ? (const float4*)bq :
                            (seg == 1) ? (const float4*)bk : (const float4*)bv;
        bsm4[tid] = src[tx];
    }
    __syncthreads();

    int tx = tid & 15, ty = tid >> 4;
    ulonglong2 acc[3][4];
    #pragma unroll
    for (int s = 0; s < 3; s++) {
        ulonglong2 b = ((ulonglong2*)bsm4)[s*16 + tx];
        #pragma unroll
        for (int r = 0; r < 4; r++) acc[s][r] = b;
    }

    #pragma unroll 4
    for (int kq = 0; kq < 16; kq++) {
        float4 aq[4];
        #pragma unroll
        for (int r = 0; r < 4; r++) aq[r] = *(float4*)&xs[(ty*4 + r)*68 + kq*4];
        #pragma unroll
        for (int e = 0; e < 4; e++) {
            int k = kq*4 + e;
            ull ap[4];
            #pragma unroll
            for (int r = 0; r < 4; r++) {
                float av = ((float*)&aq[r])[e];
                ap[r] = pack2(av, av);
            }
            #pragma unroll
            for (int s = 0; s < 3; s++) {
                ulonglong2 w2 = *(ulonglong2*)&ws4[k*48 + s*16 + tx];
                #pragma unroll
                for (int r = 0; r < 4; r++) {
                    acc[s][r].x = ffma2(ap[r], w2.x, acc[s][r].x);
                    acc[s][r].y = ffma2(ap[r], w2.y, acc[s][r].y);
                }
            }
        }
    }

    #pragma unroll
    for (int r = 0; r < 4; r++) {
        int pt = base + ty*4 + r;
        ((ulonglong2*)&g_xq[pt*64])[tx] = acc[0][r];
        ((ulonglong2*)&g_xk[pt*64])[tx] = acc[1][r];
        ((ulonglong2*)&g_xv[pt*64])[tx] = acc[2][r];
    }

    // ---- pr1 raw compute + store + stats over this block's 1024 pairs ----
    float w00 = Wp1[0], w01 = Wp1[1], w02 = Wp1[2];
    float w10 = Wp1[3], w11 = Wp1[4], w12 = Wp1[5];
    float w20 = Wp1[6], w21 = Wp1[7], w22 = Wp1[8];
    float c0 = bp1[0], c1 = bp1[1], c2 = bp1[2];
    float s0=0,s1=0,s2=0,q0=0,q1=0,q2=0;
    for (int t = tid; t < 1024; t += 256) {
        int n = base + (t >> 4);
        int g = idx[n*NS + (t & 15)];
        float r0 = p[g*3+0] - p[n*3+0];
        float r1 = p[g*3+1] - p[n*3+1];
        float r2 = p[g*3+2] - p[n*3+2];
        float v0 = c0 + r0*w00 + r1*w10 + r2*w20;
        float v1 = c1 + r0*w01 + r1*w11 + r2*w21;
        float v2 = c2 + r0*w02 + r1*w12 + r2*w22;
        g_pr1r[base*NS + t] = make_float4(v0, v1, v2, 0.f);
        s0 += v0; s1 += v1; s2 += v2;
        q0 += v0*v0; q1 += v1*v1; q2 += v2*v2;
    }
    #pragma unroll
    for (int off = 16; off; off >>= 1) {
        s0 += __shfl_xor_sync(0xffffffffu, s0, off);
        s1 += __shfl_xor_sync(0xffffffffu, s1, off);
        s2 += __shfl_xor_sync(0xffffffffu, s2, off);
        q0 += __shfl_xor_sync(0xffffffffu, q0, off);
        q1 += __shfl_xor_sync(0xffffffffu, q1, off);
        q2 += __shfl_xor_sync(0xffffffffu, q2, off);
    }
    __syncthreads();
    float* red = sm;
    int lane = tid & 31, wrp = tid >> 5;
    if (lane == 0) {
        red[wrp*6+0] = s0; red[wrp*6+1] = s1; red[wrp*6+2] = s2;
        red[wrp*6+3] = q0; red[wrp*6+4] = q1; red[wrp*6+5] = q2;
    }
    __syncthreads();
    if (tid < 6) {
        float t2 = 0.f;
        #pragma unroll
        for (int w = 0; w < 8; w++) t2 += red[w*6 + tid];
        atomicAdd(&ACC_P[tid], t2);
    }
}

// ---------------- K2: streaming BN-P + w-channel BN stats (4-way batched) ----------------
__global__ void __launch_bounds__(256) k2(
                   const int* __restrict__ idx,
                   const float* __restrict__ gp, const float* __restrict__ bpbn,
                   const float* __restrict__ Wp2, const float* __restrict__ bp2)
{
    __shared__ float4 prh4[1024];
    __shared__ float  xqn[64*64];
    __shared__ int    goff[1024];
    __shared__ float  sred[1024];
    int tid = threadIdx.x;
    int pair0 = blockIdx.x * 1024;
    int pbase = pair0 >> 4;

    for (int i = tid; i < 1024; i += 256) goff[i] = idx[pair0 + i] << 4;
    for (int i = tid; i < 4096; i += 256) xqn[i] = -g_xq[pbase*64 + i];

    float scP[3], shP[3];
    #pragma unroll
    for (int c = 0; c < 3; c++) {
        float mean = ACC_P[c] / MF;
        float var  = ACC_P[3+c] / MF - mean*mean;
        float sc   = gp[c] * rsqrtf(var + EPS);
        scP[c] = sc;
        shP[c] = bpbn[c] - mean*sc;
    }
    __syncthreads();

    #pragma unroll
    for (int kk = 0; kk < 4; kk++) {
        int t = tid + kk*256;
        float4 v = __ldg(&g_pr1r[pair0 + t]);
        float h0 = fmaxf(v.x*scP[0] + shP[0], 0.f);
        float h1 = fmaxf(v.y*scP[1] + shP[1], 0.f);
        float h2 = fmaxf(v.z*scP[2] + shP[2], 0.f);
        float4 h = make_float4(h0, h1, h2, 0.f);
        prh4[t] = h;
        g_prh4[pair0 + t] = h;
    }
    __syncthreads();

    int cq = (tid & 15) * 4;
    int lof = tid & 15;
    float4 A0q = __ldg((const float4*)&Wp2[cq]);
    float4 A1q = __ldg((const float4*)&Wp2[64 + cq]);
    float4 A2q = __ldg((const float4*)&Wp2[128 + cq]);
    float4 Bq  = __ldg((const float4*)&bp2[cq]);
    ulonglong2 A0u = *(ulonglong2*)&A0q, A1u = *(ulonglong2*)&A1q;
    ulonglong2 A2u = *(ulonglong2*)&A2q, Bu  = *(ulonglong2*)&Bq;

    ull s_lo = 0, s_hi = 0, ss_lo = 0, ss_hi = 0;
    int pl = tid >> 4;
    #pragma unroll 1
    for (int k = 0; k < 64; k += 4) {
        int t0 = pl + 16*k;
        float4 xkq[4], h4[4];
        ulonglong2 xqu[4];
        #pragma unroll
        for (int e = 0; e < 4; e++) {
            int t = t0 + 16*e;
            xkq[e] = __ldg((const float4*)g_xk + goff[t] + lof);
            h4[e]  = prh4[t];
            xqu[e] = *(ulonglong2*)&xqn[(t >> 4)*64 + cq];
        }
        #pragma unroll
        for (int e = 0; e < 4; e++) {
            ull h0p = pack2(h4[e].x, h4[e].x), h1p = pack2(h4[e].y, h4[e].y), h2p = pack2(h4[e].z, h4[e].z);
            ulonglong2 xku = *(ulonglong2*)&xkq[e];
            ull t_lo = ffma2(h2p, A2u.x, ffma2(h1p, A1u.x, ffma2(h0p, A0u.x, Bu.x)));
            ull t_hi = ffma2(h2p, A2u.y, ffma2(h1p, A1u.y, ffma2(h0p, A0u.y, Bu.y)));
            ull w_lo = fadd2(xku.x, fadd2(xqu[e].x, t_lo));
            ull w_hi = fadd2(xku.y, fadd2(xqu[e].y, t_hi));
            s_lo = fadd2(s_lo, w_lo); s_hi = fadd2(s_hi, w_hi);
            ss_lo = ffma2(w_lo, w_lo, ss_lo); ss_hi = ffma2(w_hi, w_hi, ss_hi);
        }
    }

    float v[8];
    unpack2(s_lo, v[0], v[1]); unpack2(s_hi, v[2], v[3]);
    unpack2(ss_lo, v[4], v[5]); unpack2(ss_hi, v[6], v[7]);
    #pragma unroll
    for (int i = 0; i < 8; i++) v[i] += __shfl_xor_sync(0xffffffffu, v[i], 16);
    int lane = tid & 31, wrp = tid >> 5;
    if (lane < 16) {
        #pragma unroll
        for (int i = 0; i < 8; i++) sred[lane*64 + wrp*8 + i] = v[i];
    }
    __syncthreads();
    if (tid < 128) {
        int q = tid >> 3, vi = tid & 7;
        float s = 0.f;
        #pragma unroll
        for (int w = 0; w < 8; w++) s += sred[q*64 + w*8 + vi];
        int gi = (vi < 4) ? (q*4 + vi) : (64 + q*4 + vi - 4);
        atomicAdd(&ACC_W[gi], s);
    }
}

// ---------------- K3: 16 lanes/pair, reg tables, 2-way interleaved + goff ----------------
__global__ void __launch_bounds__(256, 2) k3(
                   const int* __restrict__ idx,
                   const float* __restrict__ Wp2, const float* __restrict__ bp2,
                   const float* __restrict__ gw1, const float* __restrict__ bw1bn,
                   const float* __restrict__ Ww1, const float* __restrict__ bw1)
{
    __shared__ float xqn[32*64];
    __shared__ int   gixs[512];
    __shared__ float sS[64];
    __shared__ float wred[8*16];
    int tid = threadIdx.x;
    int lane = tid & 31, wrp = tid >> 5;
    int pair0 = blockIdx.x * 512;
    int pbase = pair0 >> 4;
    int cq = (tid & 15) * 4;
    int lof = tid & 15;
    int slot = tid >> 4;
    int P = (lane >> 2) & 3;

    if (tid < 64) {
        int c = tid;
        float mean = ACC_W[c] / MF;
        float var  = ACC_W[64 + c] / MF - mean*mean;
        sS[c] = gw1[c] * rsqrtf(var + EPS);
    }
    for (int i = tid; i < 512; i += 256) gixs[i] = idx[pair0 + i] << 4;

    ull A0u[2], A1u[2], A2u[2], Bu[2], Su[2];
    {
        float a0[4], a1[4], a2[4], bb[4], sv[4];
        #pragma unroll
        for (int e = 0; e < 4; e++) {
            int c = cq + e;
            float mean = ACC_W[c] / MF;
            float var  = ACC_W[64 + c] / MF - mean*mean;
            float sc   = gw1[c] * rsqrtf(var + EPS);
            float sh   = bw1bn[c] - mean*sc;
            sv[e] = sc;
            a0[e] = Wp2[c]*sc; a1[e] = Wp2[64+c]*sc; a2[e] = Wp2[128+c]*sc;
            bb[e] = bp2[c]*sc + sh;
        }
        A0u[0] = pack2(a0[0], a0[1]); A0u[1] = pack2(a0[2], a0[3]);
        A1u[0] = pack2(a1[0], a1[1]); A1u[1] = pack2(a1[2], a1[3]);
        A2u[0] = pack2(a2[0], a2[1]); A2u[1] = pack2(a2[2], a2[3]);
        Bu[0]  = pack2(bb[0], bb[1]); Bu[1]  = pack2(bb[2], bb[3]);
        Su[0]  = pack2(sv[0], sv[1]); Su[1]  = pack2(sv[2], sv[3]);
    }

    ull Wr[4][4];
    #pragma unroll
    for (int e = 0; e < 4; e++)
        #pragma unroll
        for (int s = 0; s < 4; s++)
            Wr[e][s] = __ldg((const ull*)Ww1 + (cq + e)*4 + (P ^ s));
    ull biasu = __ldg((const ull*)bw1 + P);
    __syncthreads();

    for (int i = tid; i < 2048; i += 256)
        xqn[i] = -g_xq[(size_t)pbase*64 + i] * sS[i & 63];
    __syncthreads();

    const ulonglong2* xkb = (const ulonglong2*)g_xk;
    ull stS = 0, stQ = 0;

    #pragma unroll 1
    for (int k = 0; k < 32; k += 2) {
        int li0 = slot + (k << 4);
        int li1 = li0 + 16;
        int pr_0 = pair0 + li0, pr_1 = pair0 + li1;
        float4 hA = __ldg(&g_prh4[pr_0]);
        float4 hB = __ldg(&g_prh4[pr_1]);
        ulonglong2 xkA = __ldg(xkb + gixs[li0] + lof);
        ulonglong2 xkB = __ldg(xkb + gixs[li1] + lof);
        ulonglong2 xqA = *(const ulonglong2*)&xqn[(k << 6) + cq];
        ulonglong2 xqB = *(const ulonglong2*)&xqn[((k + 1) << 6) + cq];

        ull a0A, a1A, a2A, a3A;
        {
            ull h0p = pack2(hA.x, hA.x), h1p = pack2(hA.y, hA.y), h2p = pack2(hA.z, hA.z);
            ull r_lo = ffma2(h2p, A2u[0], ffma2(h1p, A1u[0], ffma2(h0p, A0u[0], Bu[0])));
            ull r_hi = ffma2(h2p, A2u[1], ffma2(h1p, A1u[1], ffma2(h0p, A0u[1], Bu[1])));
            ull w_lo = ffma2(xkA.x, Su[0], fadd2(xqA.x, r_lo));
            ull w_hi = ffma2(xkA.y, Su[1], fadd2(xqA.y, r_hi));
            float w0, w1, w2, w3;
            unpack2(w_lo, w0, w1); unpack2(w_hi, w2, w3);
            ull wp0 = pack2(fmaxf(w0,0.f), fmaxf(w0,0.f));
            ull wp1 = pack2(fmaxf(w1,0.f), fmaxf(w1,0.f));
            ull wp2_ = pack2(fmaxf(w2,0.f), fmaxf(w2,0.f));
            ull wp3 = pack2(fmaxf(w3,0.f), fmaxf(w3,0.f));
            a0A = fmul2(wp0, Wr[0][0]); a1A = fmul2(wp0, Wr[0][1]);
            a2A = fmul2(wp0, Wr[0][2]); a3A = fmul2(wp0, Wr[0][3]);
            a0A = ffma2(wp1, Wr[1][0], a0A); a1A = ffma2(wp1, Wr[1][1], a1A);
            a2A = ffma2(wp1, Wr[1][2], a2A); a3A = ffma2(wp1, Wr[1][3], a3A);
            a0A = ffma2(wp2_, Wr[2][0], a0A); a1A = ffma2(wp2_, Wr[2][1], a1A);
            a2A = ffma2(wp2_, Wr[2][2], a2A); a3A = ffma2(wp2_, Wr[2][3], a3A);
            a0A = ffma2(wp3, Wr[3][0], a0A); a1A = ffma2(wp3, Wr[3][1], a1A);
            a2A = ffma2(wp3, Wr[3][2], a2A); a3A = ffma2(wp3, Wr[3][3], a3A);
        }
        ull a0B, a1B, a2B, a3B;
        {
            ull h0p = pack2(hB.x, hB.x), h1p = pack2(hB.y, hB.y), h2p = pack2(hB.z, hB.z);
            ull r_lo = ffma2(h2p, A2u[0], ffma2(h1p, A1u[0], ffma2(h0p, A0u[0], Bu[0])));
            ull r_hi = ffma2(h2p, A2u[1], ffma2(h1p, A1u[1], ffma2(h0p, A0u[1], Bu[1])));
            ull w_lo = ffma2(xkB.x, Su[0], fadd2(xqB.x, r_lo));
            ull w_hi = ffma2(xkB.y, Su[1], fadd2(xqB.y, r_hi));
            float w0, w1, w2, w3;
            unpack2(w_lo, w0, w1); unpack2(w_hi, w2, w3);
            ull wp0 = pack2(fmaxf(w0,0.f), fmaxf(w0,0.f));
            ull wp1 = pack2(fmaxf(w1,0.f), fmaxf(w1,0.f));
            ull wp2_ = pack2(fmaxf(w2,0.f), fmaxf(w2,0.f));
            ull wp3 = pack2(fmaxf(w3,0.f), fmaxf(w3,0.f));
            a0B = fmul2(wp0, Wr[0][0]); a1B = fmul2(wp0, Wr[0][1]);
            a2B = fmul2(wp0, Wr[0][2]); a3B = fmul2(wp0, Wr[0][3]);
            a0B = ffma2(wp1, Wr[1][0], a0B); a1B = ffma2(wp1, Wr[1][1], a1B);
            a2B = ffma2(wp1, Wr[1][2], a2B); a3B = ffma2(wp1, Wr[1][3], a3B);
            a0B = ffma2(wp2_, Wr[2][0], a0B); a1B = ffma2(wp2_, Wr[2][1], a1B);
            a2B = ffma2(wp2_, Wr[2][2], a2B); a3B = ffma2(wp2_, Wr[2][3], a3B);
            a0B = ffma2(wp3, Wr[3][0], a0B); a1B = ffma2(wp3, Wr[3][1], a1B);
            a2B = ffma2(wp3, Wr[3][2], a2B); a3B = ffma2(wp3, Wr[3][3], a3B);
        }

        ull tA2 = __shfl_xor_sync(0xffffffffu, a2A, 8);
        ull tB2 = __shfl_xor_sync(0xffffffffu, a2B, 8);
        ull tA3 = __shfl_xor_sync(0xffffffffu, a3A, 8);
        ull tB3 = __shfl_xor_sync(0xffffffffu, a3B, 8);
        a0A = fadd2(a0A, tA2); a0B = fadd2(a0B, tB2);
        a1A = fadd2(a1A, tA3); a1B = fadd2(a1B, tB3);
        ull uA = __shfl_xor_sync(0xffffffffu, a1A, 4);
        ull uB = __shfl_xor_sync(0xffffffffu, a1B, 4);
        a0A = fadd2(a0A, uA); a0B = fadd2(a0B, uB);
        uA = __shfl_xor_sync(0xffffffffu, a0A, 2);
        uB = __shfl_xor_sync(0xffffffffu, a0B, 2);
        a0A = fadd2(a0A, uA); a0B = fadd2(a0B, uB);
        uA = __shfl_xor_sync(0xffffffffu, a0A, 1);
        uB = __shfl_xor_sync(0xffffffffu, a0B, 1);
        a0A = fadd2(fadd2(a0A, uA), biasu);
        a0B = fadd2(fadd2(a0B, uB), biasu);

        if ((lane & 3) == 0) {
            *((ull*)g_w1 + (size_t)pr_0*4 + P) = a0A;
            *((ull*)g_w1 + (size_t)pr_1*4 + P) = a0B;
        }

        stS = fadd2(stS, fadd2(a0A, a0B));
        stQ = ffma2(a0A, a0A, stQ);
        stQ = ffma2(a0B, a0B, stQ);
    }

    stS = fadd2(stS, __shfl_xor_sync(0xffffffffu, stS, 16));
    stQ = fadd2(stQ, __shfl_xor_sync(0xffffffffu, stQ, 16));
    if (lane < 16 && (lane & 3) == 0) {
        float s0, s1, q0, q1;
        unpack2(stS, s0, s1); unpack2(stQ, q0, q1);
        wred[wrp*16 + 2*P]     = s0;
        wred[wrp*16 + 2*P + 1] = s1;
        wred[wrp*16 + 8 + 2*P]     = q0;
        wred[wrp*16 + 8 + 2*P + 1] = q1;
    }
    __syncthreads();
    if (tid < 16) {
        float s = 0.f;
        #pragma unroll
        for (int w = 0; w < 8; w++) s += wred[w*16 + tid];
        atomicAdd(&ACC_U[tid], s);
    }
}

// ---------------- K4: bn2+relu -> @Ww2 -> softmax -> factored aggregate ----------------
__global__ void __launch_bounds__(256) k4(
                   const int* __restrict__ idx,
                   const float* __restrict__ Wp2, const float* __restrict__ bp2,
                   const float* __restrict__ gw2, const float* __restrict__ bw2bn,
                   const float* __restrict__ Ww2, const float* __restrict__ bw2,
                   float* __restrict__ out)
{
    __shared__ float  hs[4][128];
    __shared__ float  w2s[4][128];   // [j*8 + t] (broadcast-friendly)
    __shared__ float4 prs4[4][16];   // packed {h0,h1,h2,0} per neighbor
    __shared__ float4 hbar[4][8];    // Σ_j w_j[t] * h_j  per t
    __shared__ int    gix4[4][16];   // g*64
    __shared__ float  wp2s[192], bp2s[64], wws[64], bws[8];
    int tid = threadIdx.x;
    int sub = tid >> 6, ct = tid & 63;
    int n = blockIdx.x*4 + sub;

    for (int i = tid; i < 192; i += 256) wp2s[i] = Wp2[i];
    if (tid < 64) { bp2s[tid] = bp2[tid]; wws[tid] = Ww2[tid]; }
    if (tid < 8)  bws[tid] = bw2[tid];

    int u = ct & 7;
    float mean = ACC_U[u] / MF;
    float var  = ACC_U[8 + u] / MF - mean*mean;
    float sc2  = gw2[u] * rsqrtf(var + EPS);
    float sh2  = bw2bn[u] - mean*sc2;

    hs[sub][ct]      = fmaxf(g_w1[n*128 + ct]*sc2 + sh2, 0.f);
    hs[sub][ct + 64] = fmaxf(g_w1[n*128 + ct + 64]*sc2 + sh2, 0.f);
    if (ct < 16) {
        gix4[sub][ct] = idx[n*16 + ct] << 6;
        prs4[sub][ct] = g_prh4[n*16 + ct];
    }
    __syncthreads();

    #pragma unroll
    for (int o = ct; o < 128; o += 64) {
        int j = o >> 3, t = o & 7;
        float v = bws[t];
        #pragma unroll
        for (int uu = 0; uu < 8; uu++) v += hs[sub][j*8 + uu] * wws[uu*8 + t];
        w2s[sub][o] = v;
    }
    __syncthreads();

    if (ct < 8) {
        int t = ct;
        float m = -1e30f;
        #pragma unroll
        for (int j = 0; j < 16; j++) m = fmaxf(m, w2s[sub][j*8 + t]);
        float e[16], ssum = 0.f;
        #pragma unroll
        for (int j = 0; j < 16; j++) { e[j] = __expf(w2s[sub][j*8 + t] - m); ssum += e[j]; }
        float inv = 1.f / ssum;
        float H0 = 0.f, H1 = 0.f, H2 = 0.f;
        #pragma unroll
        for (int j = 0; j < 16; j++) {
            float wj = e[j] * inv;
            w2s[sub][j*8 + t] = wj;
            float4 h = prs4[sub][j];
            H0 = fmaf(h.x, wj, H0);
            H1 = fmaf(h.y, wj, H1);
            H2 = fmaf(h.z, wj, H2);
        }
        hbar[sub][t] = make_float4(H0, H1, H2, 0.f);
    }
    __syncthreads();

    // factored aggregation: acc = Σ_j xv_j * w_j; pr contribution via hbar
    int t = ct & 7;
    float acc = 0.f;
    #pragma unroll
    for (int j = 0; j < 16; j++) {
        float v = __ldg(&g_xv[gix4[sub][j] + ct]);
        acc = fmaf(v, w2s[sub][j*8 + t], acc);
    }
    float4 H = hbar[sub][t];
    float a0 = wp2s[ct], a1 = wp2s[64 + ct], a2 = wp2s[128 + ct], bb = bp2s[ct];
    acc += fmaf(H.z, a2, fmaf(H.y, a1, fmaf(H.x, a0, bb)));
    out[n*64 + ct] = acc;
}

// ---------------- launch ----------------
extern "C" void kernel_launch(void* const* d_in, const int* in_sizes, int n_in,
                              void* d_out, int out_size)
{
    const float* p    = (const float*)d_in[0];
    const float* x    = (const float*)d_in[1];
    const int*   idx  = (const int*)d_in[2];
    const float* Wq   = (const float*)d_in[3];
    const float* bq   = (const float*)d_in[4];
    const float* Wk   = (const float*)d_in[5];
    const float* bk   = (const float*)d_in[6];
    const float* Wv   = (const float*)d_in[7];
    const float* bv   = (const float*)d_in[8];
    const float* Wp1  = (const float*)d_in[9];
    const float* bp1  = (const float*)d_in[10];
    const float* gp   = (const float*)d_in[11];
    const float* bpbn = (const float*)d_in[12];
    const float* Wp2  = (const float*)d_in[13];
    const float* bp2  = (const float*)d_in[14];
    const float* gw1  = (const float*)d_in[15];
    const float* bw1bn= (const float*)d_in[16];
    const float* Ww1  = (const float*)d_in[17];
    const float* bw1  = (const float*)d_in[18];
    const float* gw2  = (const float*)d_in[19];
    const float* bw2bn= (const float*)d_in[20];
    const float* Ww2  = (const float*)d_in[21];
    const float* bw2  = (const float*)d_in[22];
    float* out = (float*)d_out;

    size_t smem1 = (size_t)(64*48*4 + 64*68 + 48*4) * 4;  // ~66KB
    cudaFuncSetAttribute(k1, cudaFuncAttributeMaxDynamicSharedMemorySize, (int)smem1);

    void* accPtr = nullptr;
    cudaGetSymbolAddress(&accPtr, g_acc);
    cudaMemsetAsync(accPtr, 0, 152 * sizeof(float));

    k1<<<1024, 256, smem1>>>(x, p, idx, Wq, bq, Wk, bk, Wv, bv, Wp1, bp1);
    k2<<<1024, 256>>>(idx, gp, bpbn, Wp2, bp2);
    k3<<<2048, 256>>>(idx, Wp2, bp2, gw1, bw1bn, Ww1, bw1);
    k4<<<16384, 256>>>(idx, Wp2, bp2, gw2, bw2bn, Ww2, bw2, out);
}

// round 16
// speedup vs baseline: 1.1312x; 1.0755x over previous
#include <cuda_runtime.h>

#define NPTS 65536
#define NS 16
#define NPAIR (NPTS*NS)
#define MF 1048576.0f
#define EPS 1e-5f

typedef unsigned long long ull;

__device__ __forceinline__ ull ffma2(ull a, ull b, ull c) {
    ull d; asm("fma.rn.f32x2 %0,%1,%2,%3;" : "=l"(d) : "l"(a), "l"(b), "l"(c)); return d;
}
__device__ __forceinline__ ull fmul2(ull a, ull b) {
    ull d; asm("mul.rn.f32x2 %0,%1,%2;" : "=l"(d) : "l"(a), "l"(b)); return d;
}
__device__ __forceinline__ ull fadd2(ull a, ull b) {
    ull d; asm("add.rn.f32x2 %0,%1,%2;" : "=l"(d) : "l"(a), "l"(b)); return d;
}
__device__ __forceinline__ ull pack2(float lo, float hi) {
    ull d; asm("mov.b64 %0,{%1,%2};" : "=l"(d) : "f"(lo), "f"(hi)); return d;
}
__device__ __forceinline__ void unpack2(ull v, float& lo, float& hi) {
    asm("mov.b64 {%0,%1},%2;" : "=f"(lo), "=f"(hi) : "l"(v));
}

// ---------------- scratch ----------------
__device__ float  g_xq[NPTS*64];
__device__ float  g_xk[NPTS*64];
__device__ float  g_xv[NPTS*64];
__device__ float4 g_pr1r[NPAIR];
__device__ float4 g_prh4[NPAIR];
__device__ float  g_w1[NPAIR*8];
__device__ float  g_acc[152];
#define ACC_P (g_acc)
#define ACC_W (g_acc + 8)
#define ACC_U (g_acc + 136)

// ---------------- K1: qkv GEMM (64 pts/block) + pr1 raw store + BN-P stats ----------------
__global__ void __launch_bounds__(256) k1(
                   const float* __restrict__ x, const float* __restrict__ p,
                   const int* __restrict__ idx,
                   const float* __restrict__ Wq, const float* __restrict__ bq,
                   const float* __restrict__ Wk, const float* __restrict__ bk,
                   const float* __restrict__ Wv, const float* __restrict__ bv,
                   const float* __restrict__ Wp1, const float* __restrict__ bp1)
{
    extern __shared__ float sm[];
    float4* ws4  = (float4*)sm;
    float*  xs   = sm + 64*48*4;
    float4* bsm4 = (float4*)(xs + 64*68);
    int tid = threadIdx.x;
    int base = blockIdx.x * 64;

    for (int i = tid; i < 64*48; i += 256) {
        int k = i / 48, r = i - k*48;
        int seg = r >> 4, tx = r & 15;
        const float4* src = (seg == 0) ? (const float4*)Wq :
                            (seg == 1) ? (const float4*)Wk : (const float4*)Wv;
        ws4[i] = src[k*16 + tx];
    }
    {
        float4* xs4 = (float4*)xs;
        for (int i = tid; i < 64*16; i += 256) {
            int pt = i >> 4, kk = i & 15;
            xs4[pt*17 + kk] = ((const float4*)x)[(base + pt)*16 + kk];
        }
    }
    if (tid < 48) {
        int seg = tid >> 4, tx = tid & 15;
        const float4* src = (seg == 0) ? (const float4*)bq :
                            (seg == 1) ? (const float4*)bk : (const float4*)bv;
        bsm4[tid] = src[tx];
    }
    __syncthreads();

    int tx = tid & 15, ty = tid >> 4;
    ulonglong2 acc[3][4];
    #pragma unroll
    for (int s = 0; s < 3; s++) {
        ulonglong2 b = ((ulonglong2*)bsm4)[s*16 + tx];
        #pragma unroll
        for (int r = 0; r < 4; r++) acc[s][r] = b;
    }

    #pragma unroll 4
    for (int kq = 0; kq < 16; kq++) {
        float4 aq[4];
        #pragma unroll
        for (int r = 0; r < 4; r++) aq[r] = *(float4*)&xs[(ty*4 + r)*68 + kq*4];
        #pragma unroll
        for (int e = 0; e < 4; e++) {
            int k = kq*4 + e;
            ull ap[4];
            #pragma unroll
            for (int r = 0; r < 4; r++) {
                float av = ((float*)&aq[r])[e];
                ap[r] = pack2(av, av);
            }
            #pragma unroll
            for (int s = 0; s < 3; s++) {
                ulonglong2 w2 = *(ulonglong2*)&ws4[k*48 + s*16 + tx];
                #pragma unroll
                for (int r = 0; r < 4; r++) {
                    acc[s][r].x = ffma2(ap[r], w2.x, acc[s][r].x);
                    acc[s][r].y = ffma2(ap[r], w2.y, acc[s][r].y);
                }
            }
        }
    }

    #pragma unroll
    for (int r = 0; r < 4; r++) {
        int pt = base + ty*4 + r;
        ((ulonglong2*)&g_xq[pt*64])[tx] = acc[0][r];
        ((ulonglong2*)&g_xk[pt*64])[tx] = acc[1][r];
        ((ulonglong2*)&g_xv[pt*64])[tx] = acc[2][r];
    }

    float w00 = Wp1[0], w01 = Wp1[1], w02 = Wp1[2];
    float w10 = Wp1[3], w11 = Wp1[4], w12 = Wp1[5];
    float w20 = Wp1[6], w21 = Wp1[7], w22 = Wp1[8];
    float c0 = bp1[0], c1 = bp1[1], c2 = bp1[2];
    float s0=0,s1=0,s2=0,q0=0,q1=0,q2=0;
    for (int t = tid; t < 1024; t += 256) {
        int n = base + (t >> 4);
        int g = idx[n*NS + (t & 15)];
        float r0 = p[g*3+0] - p[n*3+0];
        float r1 = p[g*3+1] - p[n*3+1];
        float r2 = p[g*3+2] - p[n*3+2];
        float v0 = c0 + r0*w00 + r1*w10 + r2*w20;
        float v1 = c1 + r0*w01 + r1*w11 + r2*w21;
        float v2 = c2 + r0*w02 + r1*w12 + r2*w22;
        g_pr1r[base*NS + t] = make_float4(v0, v1, v2, 0.f);
        s0 += v0; s1 += v1; s2 += v2;
        q0 += v0*v0; q1 += v1*v1; q2 += v2*v2;
    }
    #pragma unroll
    for (int off = 16; off; off >>= 1) {
        s0 += __shfl_xor_sync(0xffffffffu, s0, off);
        s1 += __shfl_xor_sync(0xffffffffu, s1, off);
        s2 += __shfl_xor_sync(0xffffffffu, s2, off);
        q0 += __shfl_xor_sync(0xffffffffu, q0, off);
        q1 += __shfl_xor_sync(0xffffffffu, q1, off);
        q2 += __shfl_xor_sync(0xffffffffu, q2, off);
    }
    __syncthreads();
    float* red = sm;
    int lane = tid & 31, wrp = tid >> 5;
    if (lane == 0) {
        red[wrp*6+0] = s0; red[wrp*6+1] = s1; red[wrp*6+2] = s2;
        red[wrp*6+3] = q0; red[wrp*6+4] = q1; red[wrp*6+5] = q2;
    }
    __syncthreads();
    if (tid < 6) {
        float t2 = 0.f;
        #pragma unroll
        for (int w = 0; w < 8; w++) t2 += red[w*6 + tid];
        atomicAdd(&ACC_P[tid], t2);
    }
}

// ---------------- K2: streaming BN-P + w-channel BN stats (4-way batched) ----------------
__global__ void __launch_bounds__(256) k2(
                   const int* __restrict__ idx,
                   const float* __restrict__ gp, const float* __restrict__ bpbn,
                   const float* __restrict__ Wp2, const float* __restrict__ bp2)
{
    __shared__ float4 prh4[1024];
    __shared__ float  xqn[64*64];
    __shared__ int    goff[1024];
    __shared__ float  sred[1024];
    int tid = threadIdx.x;
    int pair0 = blockIdx.x * 1024;
    int pbase = pair0 >> 4;

    for (int i = tid; i < 1024; i += 256) goff[i] = idx[pair0 + i] << 4;
    for (int i = tid; i < 4096; i += 256) xqn[i] = -g_xq[pbase*64 + i];

    float scP[3], shP[3];
    #pragma unroll
    for (int c = 0; c < 3; c++) {
        float mean = ACC_P[c] / MF;
        float var  = ACC_P[3+c] / MF - mean*mean;
        float sc   = gp[c] * rsqrtf(var + EPS);
        scP[c] = sc;
        shP[c] = bpbn[c] - mean*sc;
    }
    __syncthreads();

    #pragma unroll
    for (int kk = 0; kk < 4; kk++) {
        int t = tid + kk*256;
        float4 v = __ldg(&g_pr1r[pair0 + t]);
        float h0 = fmaxf(v.x*scP[0] + shP[0], 0.f);
        float h1 = fmaxf(v.y*scP[1] + shP[1], 0.f);
        float h2 = fmaxf(v.z*scP[2] + shP[2], 0.f);
        float4 h = make_float4(h0, h1, h2, 0.f);
        prh4[t] = h;
        g_prh4[pair0 + t] = h;
    }
    __syncthreads();

    int cq = (tid & 15) * 4;
    int lof = tid & 15;
    float4 A0q = __ldg((const float4*)&Wp2[cq]);
    float4 A1q = __ldg((const float4*)&Wp2[64 + cq]);
    float4 A2q = __ldg((const float4*)&Wp2[128 + cq]);
    float4 Bq  = __ldg((const float4*)&bp2[cq]);
    ulonglong2 A0u = *(ulonglong2*)&A0q, A1u = *(ulonglong2*)&A1q;
    ulonglong2 A2u = *(ulonglong2*)&A2q, Bu  = *(ulonglong2*)&Bq;

    ull s_lo = 0, s_hi = 0, ss_lo = 0, ss_hi = 0;
    int pl = tid >> 4;
    #pragma unroll 1
    for (int k = 0; k < 64; k += 4) {
        int t0 = pl + 16*k;
        float4 xkq[4], h4[4];
        ulonglong2 xqu[4];
        #pragma unroll
        for (int e = 0; e < 4; e++) {
            int t = t0 + 16*e;
            xkq[e] = __ldg((const float4*)g_xk + goff[t] + lof);
            h4[e]  = prh4[t];
            xqu[e] = *(ulonglong2*)&xqn[(t >> 4)*64 + cq];
        }
        #pragma unroll
        for (int e = 0; e < 4; e++) {
            ull h0p = pack2(h4[e].x, h4[e].x), h1p = pack2(h4[e].y, h4[e].y), h2p = pack2(h4[e].z, h4[e].z);
            ulonglong2 xku = *(ulonglong2*)&xkq[e];
            ull t_lo = ffma2(h2p, A2u.x, ffma2(h1p, A1u.x, ffma2(h0p, A0u.x, Bu.x)));
            ull t_hi = ffma2(h2p, A2u.y, ffma2(h1p, A1u.y, ffma2(h0p, A0u.y, Bu.y)));
            ull w_lo = fadd2(xku.x, fadd2(xqu[e].x, t_lo));
            ull w_hi = fadd2(xku.y, fadd2(xqu[e].y, t_hi));
            s_lo = fadd2(s_lo, w_lo); s_hi = fadd2(s_hi, w_hi);
            ss_lo = ffma2(w_lo, w_lo, ss_lo); ss_hi = ffma2(w_hi, w_hi, ss_hi);
        }
    }

    float v[8];
    unpack2(s_lo, v[0], v[1]); unpack2(s_hi, v[2], v[3]);
    unpack2(ss_lo, v[4], v[5]); unpack2(ss_hi, v[6], v[7]);
    #pragma unroll
    for (int i = 0; i < 8; i++) v[i] += __shfl_xor_sync(0xffffffffu, v[i], 16);
    int lane = tid & 31, wrp = tid >> 5;
    if (lane < 16) {
        #pragma unroll
        for (int i = 0; i < 8; i++) sred[lane*64 + wrp*8 + i] = v[i];
    }
    __syncthreads();
    if (tid < 128) {
        int q = tid >> 3, vi = tid & 7;
        float s = 0.f;
        #pragma unroll
        for (int w = 0; w < 8; w++) s += sred[q*64 + w*8 + vi];
        int gi = (vi < 4) ? (q*4 + vi) : (64 + q*4 + vi - 4);
        atomicAdd(&ACC_W[gi], s);
    }
}

// ---------------- K3: 16 lanes/pair, reg tables, 2-way interleaved + goff ----------------
__global__ void __launch_bounds__(256, 2) k3(
                   const int* __restrict__ idx,
                   const float* __restrict__ Wp2, const float* __restrict__ bp2,
                   const float* __restrict__ gw1, const float* __restrict__ bw1bn,
                   const float* __restrict__ Ww1, const float* __restrict__ bw1)
{
    __shared__ float xqn[32*64];
    __shared__ int   gixs[512];
    __shared__ float sS[64];
    __shared__ float wred[8*16];
    int tid = threadIdx.x;
    int lane = tid & 31, wrp = tid >> 5;
    int pair0 = blockIdx.x * 512;
    int pbase = pair0 >> 4;
    int cq = (tid & 15) * 4;
    int lof = tid & 15;
    int slot = tid >> 4;
    int P = (lane >> 2) & 3;

    if (tid < 64) {
        int c = tid;
        float mean = ACC_W[c] / MF;
        float var  = ACC_W[64 + c] / MF - mean*mean;
        sS[c] = gw1[c] * rsqrtf(var + EPS);
    }
    for (int i = tid; i < 512; i += 256) gixs[i] = idx[pair0 + i] << 4;

    ull A0u[2], A1u[2], A2u[2], Bu[2], Su[2];
    {
        float a0[4], a1[4], a2[4], bb[4], sv[4];
        #pragma unroll
        for (int e = 0; e < 4; e++) {
            int c = cq + e;
            float mean = ACC_W[c] / MF;
            float var  = ACC_W[64 + c] / MF - mean*mean;
            float sc   = gw1[c] * rsqrtf(var + EPS);
            float sh   = bw1bn[c] - mean*sc;
            sv[e] = sc;
            a0[e] = Wp2[c]*sc; a1[e] = Wp2[64+c]*sc; a2[e] = Wp2[128+c]*sc;
            bb[e] = bp2[c]*sc + sh;
        }
        A0u[0] = pack2(a0[0], a0[1]); A0u[1] = pack2(a0[2], a0[3]);
        A1u[0] = pack2(a1[0], a1[1]); A1u[1] = pack2(a1[2], a1[3]);
        A2u[0] = pack2(a2[0], a2[1]); A2u[1] = pack2(a2[2], a2[3]);
        Bu[0]  = pack2(bb[0], bb[1]); Bu[1]  = pack2(bb[2], bb[3]);
        Su[0]  = pack2(sv[0], sv[1]); Su[1]  = pack2(sv[2], sv[3]);
    }

    ull Wr[4][4];
    #pragma unroll
    for (int e = 0; e < 4; e++)
        #pragma unroll
        for (int s = 0; s < 4; s++)
            Wr[e][s] = __ldg((const ull*)Ww1 + (cq + e)*4 + (P ^ s));
    ull biasu = __ldg((const ull*)bw1 + P);
    __syncthreads();

    for (int i = tid; i < 2048; i += 256)
        xqn[i] = -g_xq[(size_t)pbase*64 + i] * sS[i & 63];
    __syncthreads();

    const ulonglong2* xkb = (const ulonglong2*)g_xk;
    ull stS = 0, stQ = 0;

    #pragma unroll 1
    for (int k = 0; k < 32; k += 2) {
        int li0 = slot + (k << 4);
        int li1 = li0 + 16;
        int pr_0 = pair0 + li0, pr_1 = pair0 + li1;
        float4 hA = __ldg(&g_prh4[pr_0]);
        float4 hB = __ldg(&g_prh4[pr_1]);
        ulonglong2 xkA = __ldg(xkb + gixs[li0] + lof);
        ulonglong2 xkB = __ldg(xkb + gixs[li1] + lof);
        ulonglong2 xqA = *(const ulonglong2*)&xqn[(k << 6) + cq];
        ulonglong2 xqB = *(const ulonglong2*)&xqn[((k + 1) << 6) + cq];

        ull a0A, a1A, a2A, a3A;
        {
            ull h0p = pack2(hA.x, hA.x), h1p = pack2(hA.y, hA.y), h2p = pack2(hA.z, hA.z);
            ull r_lo = ffma2(h2p, A2u[0], ffma2(h1p, A1u[0], ffma2(h0p, A0u[0], Bu[0])));
            ull r_hi = ffma2(h2p, A2u[1], ffma2(h1p, A1u[1], ffma2(h0p, A0u[1], Bu[1])));
            ull w_lo = ffma2(xkA.x, Su[0], fadd2(xqA.x, r_lo));
            ull w_hi = ffma2(xkA.y, Su[1], fadd2(xqA.y, r_hi));
            float w0, w1, w2, w3;
            unpack2(w_lo, w0, w1); unpack2(w_hi, w2, w3);
            ull wp0 = pack2(fmaxf(w0,0.f), fmaxf(w0,0.f));
            ull wp1 = pack2(fmaxf(w1,0.f), fmaxf(w1,0.f));
            ull wp2_ = pack2(fmaxf(w2,0.f), fmaxf(w2,0.f));
            ull wp3 = pack2(fmaxf(w3,0.f), fmaxf(w3,0.f));
            a0A = fmul2(wp0, Wr[0][0]); a1A = fmul2(wp0, Wr[0][1]);
            a2A = fmul2(wp0, Wr[0][2]); a3A = fmul2(wp0, Wr[0][3]);
            a0A = ffma2(wp1, Wr[1][0], a0A); a1A = ffma2(wp1, Wr[1][1], a1A);
            a2A = ffma2(wp1, Wr[1][2], a2A); a3A = ffma2(wp1, Wr[1][3], a3A);
            a0A = ffma2(wp2_, Wr[2][0], a0A); a1A = ffma2(wp2_, Wr[2][1], a1A);
            a2A = ffma2(wp2_, Wr[2][2], a2A); a3A = ffma2(wp2_, Wr[2][3], a3A);
            a0A = ffma2(wp3, Wr[3][0], a0A); a1A = ffma2(wp3, Wr[3][1], a1A);
            a2A = ffma2(wp3, Wr[3][2], a2A); a3A = ffma2(wp3, Wr[3][3], a3A);
        }
        ull a0B, a1B, a2B, a3B;
        {
            ull h0p = pack2(hB.x, hB.x), h1p = pack2(hB.y, hB.y), h2p = pack2(hB.z, hB.z);
            ull r_lo = ffma2(h2p, A2u[0], ffma2(h1p, A1u[0], ffma2(h0p, A0u[0], Bu[0])));
            ull r_hi = ffma2(h2p, A2u[1], ffma2(h1p, A1u[1], ffma2(h0p, A0u[1], Bu[1])));
            ull w_lo = ffma2(xkB.x, Su[0], fadd2(xqB.x, r_lo));
            ull w_hi = ffma2(xkB.y, Su[1], fadd2(xqB.y, r_hi));
            float w0, w1, w2, w3;
            unpack2(w_lo, w0, w1); unpack2(w_hi, w2, w3);
            ull wp0 = pack2(fmaxf(w0,0.f), fmaxf(w0,0.f));
            ull wp1 = pack2(fmaxf(w1,0.f), fmaxf(w1,0.f));
            ull wp2_ = pack2(fmaxf(w2,0.f), fmaxf(w2,0.f));
            ull wp3 = pack2(fmaxf(w3,0.f), fmaxf(w3,0.f));
            a0B = fmul2(wp0, Wr[0][0]); a1B = fmul2(wp0, Wr[0][1]);
            a2B = fmul2(wp0, Wr[0][2]); a3B = fmul2(wp0, Wr[0][3]);
            a0B = ffma2(wp1, Wr[1][0], a0B); a1B = ffma2(wp1, Wr[1][1], a1B);
            a2B = ffma2(wp1, Wr[1][2], a2B); a3B = ffma2(wp1, Wr[1][3], a3B);
            a0B = ffma2(wp2_, Wr[2][0], a0B); a1B = ffma2(wp2_, Wr[2][1], a1B);
            a2B = ffma2(wp2_, Wr[2][2], a2B); a3B = ffma2(wp2_, Wr[2][3], a3B);
            a0B = ffma2(wp3, Wr[3][0], a0B); a1B = ffma2(wp3, Wr[3][1], a1B);
            a2B = ffma2(wp3, Wr[3][2], a2B); a3B = ffma2(wp3, Wr[3][3], a3B);
        }

        ull tA2 = __shfl_xor_sync(0xffffffffu, a2A, 8);
        ull tB2 = __shfl_xor_sync(0xffffffffu, a2B, 8);
        ull tA3 = __shfl_xor_sync(0xffffffffu, a3A, 8);
        ull tB3 = __shfl_xor_sync(0xffffffffu, a3B, 8);
        a0A = fadd2(a0A, tA2); a0B = fadd2(a0B, tB2);
        a1A = fadd2(a1A, tA3); a1B = fadd2(a1B, tB3);
        ull uA = __shfl_xor_sync(0xffffffffu, a1A, 4);
        ull uB = __shfl_xor_sync(0xffffffffu, a1B, 4);
        a0A = fadd2(a0A, uA); a0B = fadd2(a0B, uB);
        uA = __shfl_xor_sync(0xffffffffu, a0A, 2);
        uB = __shfl_xor_sync(0xffffffffu, a0B, 2);
        a0A = fadd2(a0A, uA); a0B = fadd2(a0B, uB);
        uA = __shfl_xor_sync(0xffffffffu, a0A, 1);
        uB = __shfl_xor_sync(0xffffffffu, a0B, 1);
        a0A = fadd2(fadd2(a0A, uA), biasu);
        a0B = fadd2(fadd2(a0B, uB), biasu);

        if ((lane & 3) == 0) {
            *((ull*)g_w1 + (size_t)pr_0*4 + P) = a0A;
            *((ull*)g_w1 + (size_t)pr_1*4 + P) = a0B;
        }

        stS = fadd2(stS, fadd2(a0A, a0B));
        stQ = ffma2(a0A, a0A, stQ);
        stQ = ffma2(a0B, a0B, stQ);
    }

    stS = fadd2(stS, __shfl_xor_sync(0xffffffffu, stS, 16));
    stQ = fadd2(stQ, __shfl_xor_sync(0xffffffffu, stQ, 16));
    if (lane < 16 && (lane & 3) == 0) {
        float s0, s1, q0, q1;
        unpack2(stS, s0, s1); unpack2(stQ, q0, q1);
        wred[wrp*16 + 2*P]     = s0;
        wred[wrp*16 + 2*P + 1] = s1;
        wred[wrp*16 + 8 + 2*P]     = q0;
        wred[wrp*16 + 8 + 2*P + 1] = q1;
    }
    __syncthreads();
    if (tid < 16) {
        float s = 0.f;
        #pragma unroll
        for (int w = 0; w < 8; w++) s += wred[w*16 + tid];
        atomicAdd(&ACC_U[tid], s);
    }
}

// ---------------- K4: warp-per-point, f32x2 channel pairs ----------------
// grid 8192, block 256: 8 points per block, warp w = point blk*8 + w
__global__ void __launch_bounds__(256) k4(
                   const int* __restrict__ idx,
                   const float* __restrict__ Wp2, const float* __restrict__ bp2,
                   const float* __restrict__ gw2, const float* __restrict__ bw2bn,
                   const float* __restrict__ Ww2, const float* __restrict__ bw2,
                   float* __restrict__ out)
{
    __shared__ __align__(16) float hs[8][128];
    __shared__ __align__(16) float w2s[8][128];   // logits then softmax weights, [j*8+t]
    __shared__ float4 prs4[8][16];
    __shared__ float4 hbar[8][8];
    __shared__ int    gixs[8][16];                // g*32 (ull-row offset into g_xv)
    __shared__ __align__(16) float wp2s[192], bp2s[64], wws[64], bws[8];
    int tid = threadIdx.x;
    int w = tid >> 5, lane = tid & 31;
    int n = blockIdx.x*8 + w;

    if (tid < 192) wp2s[tid] = Wp2[tid];
    if (tid < 64) { bp2s[tid] = bp2[tid]; wws[tid] = Ww2[tid]; }
    if (tid < 8)  bws[tid] = bw2[tid];

    // per-point loads by owning warp
    if (lane < 16) {
        gixs[w][lane] = idx[n*16 + lane] << 5;
        prs4[w][lane] = g_prh4[n*16 + lane];
    }

    // BN constants for channel pair (2*lane, 2*lane+1): u0 = (2*lane)&7, u0+1
    int u0 = (2*lane) & 7;
    float mean0 = ACC_U[u0] / MF,     var0 = ACC_U[8+u0] / MF - mean0*mean0;
    float mean1 = ACC_U[u0+1] / MF,   var1 = ACC_U[8+u0+1] / MF - mean1*mean1;
    float sca = gw2[u0]   * rsqrtf(var0 + EPS);
    float scb = gw2[u0+1] * rsqrtf(var1 + EPS);
    ull scp = pack2(sca, scb);
    ull shp = pack2(bw2bn[u0] - mean0*sca, bw2bn[u0+1] - mean1*scb);

    // fused BN+relu load of w1 (two ull per lane)
    {
        const ull* w1row = (const ull*)(g_w1 + (size_t)n*128);
        ull v0 = __ldg(w1row + lane);
        ull v1 = __ldg(w1row + 32 + lane);
        ull h0 = ffma2(v0, scp, shp);
        ull h1 = ffma2(v1, scp, shp);
        float a, b;
        unpack2(h0, a, b);
        *(ull*)&hs[w][2*lane] = pack2(fmaxf(a,0.f), fmaxf(b,0.f));
        unpack2(h1, a, b);
        *(ull*)&hs[w][64 + 2*lane] = pack2(fmaxf(a,0.f), fmaxf(b,0.f));
    }
    __syncthreads();   // constants + hs/gix/prs visible

    // GEMM: lane computes logits for j = lane>>1, t-pairs tp0 = 2*(lane&1), tp1 = tp0+1
    {
        int j = lane >> 1;
        int tp0 = (lane & 1) * 2, tp1 = tp0 + 1;
        ull acc0 = ((const ull*)bws)[tp0];
        ull acc1 = ((const ull*)bws)[tp1];
        const float* hrow = &hs[w][j*8];
        #pragma unroll
        for (int u = 0; u < 8; u++) {
            float h = hrow[u];
            ull hp = pack2(h, h);
            acc0 = ffma2(hp, *(const ull*)&wws[u*8 + 2*tp0], acc0);
            acc1 = ffma2(hp, *(const ull*)&wws[u*8 + 2*tp1], acc1);
        }
        *(ull*)&w2s[w][j*8 + 2*tp0] = acc0;
        *(ull*)&w2s[w][j*8 + 2*tp1] = acc1;
    }
    __syncwarp();

    // softmax over j per t (lanes 0..7) + hbar
    if (lane < 8) {
        int t = lane;
        float m = -1e30f;
        #pragma unroll
        for (int j = 0; j < 16; j++) m = fmaxf(m, w2s[w][j*8 + t]);
        float e[16], ssum = 0.f;
        #pragma unroll
        for (int j = 0; j < 16; j++) { e[j] = __expf(w2s[w][j*8 + t] - m); ssum += e[j]; }
        float inv = 1.f / ssum;
        float H0 = 0.f, H1 = 0.f, H2 = 0.f;
        #pragma unroll
        for (int j = 0; j < 16; j++) {
            float wj = e[j] * inv;
            w2s[w][j*8 + t] = wj;
            float4 h = prs4[w][j];
            H0 = fmaf(h.x, wj, H0);
            H1 = fmaf(h.y, wj, H1);
            H2 = fmaf(h.z, wj, H2);
        }
        hbar[w][t] = make_float4(H0, H1, H2, 0.f);
    }
    __syncwarp();

    // aggregation: lane owns channels 2*lane, 2*lane+1
    {
        const ull* xvb = (const ull*)g_xv;
        const ull* wrow = (const ull*)&w2s[w][0];   // ull index j*4 + tp
        int tp = lane & 3;                          // = ((2*lane)&7)>>1
        ull acc = 0;
        #pragma unroll
        for (int j = 0; j < 16; j++) {
            ull xv2 = __ldg(xvb + gixs[w][j] + lane);
            acc = ffma2(xv2, wrow[j*4 + tp], acc);
        }
        // pr contribution via hbar
        float4 Ha = hbar[w][u0];
        float4 Hb = hbar[w][u0 + 1];
        ull H0p = pack2(Ha.x, Hb.x);
        ull H1p = pack2(Ha.y, Hb.y);
        ull H2p = pack2(Ha.z, Hb.z);
        ull A0 = *(const ull*)&wp2s[2*lane];
        ull A1 = *(const ull*)&wp2s[64 + 2*lane];
        ull A2 = *(const ull*)&wp2s[128 + 2*lane];
        ull Bb = *(const ull*)&bp2s[2*lane];
        ull pr = ffma2(H2p, A2, ffma2(H1p, A1, ffma2(H0p, A0, Bb)));
        acc = fadd2(acc, pr);
        ((ull*)out)[(size_t)n*32 + lane] = acc;
    }
}

// ---------------- launch ----------------
extern "C" void kernel_launch(void* const* d_in, const int* in_sizes, int n_in,
                              void* d_out, int out_size)
{
    const float* p    = (const float*)d_in[0];
    const float* x    = (const float*)d_in[1];
    const int*   idx  = (const int*)d_in[2];
    const float* Wq   = (const float*)d_in[3];
    const float* bq   = (const float*)d_in[4];
    const float* Wk   = (const float*)d_in[5];
    const float* bk   = (const float*)d_in[6];
    const float* Wv   = (const float*)d_in[7];
    const float* bv   = (const float*)d_in[8];
    const float* Wp1  = (const float*)d_in[9];
    const float* bp1  = (const float*)d_in[10];
    const float* gp   = (const float*)d_in[11];
    const float* bpbn = (const float*)d_in[12];
    const float* Wp2  = (const float*)d_in[13];
    const float* bp2  = (const float*)d_in[14];
    const float* gw1  = (const float*)d_in[15];
    const float* bw1bn= (const float*)d_in[16];
    const float* Ww1  = (const float*)d_in[17];
    const float* bw1  = (const float*)d_in[18];
    const float* gw2  = (const float*)d_in[19];
    const float* bw2bn= (const float*)d_in[20];
    const float* Ww2  = (const float*)d_in[21];
    const float* bw2  = (const float*)d_in[22];
    float* out = (float*)d_out;

    size_t smem1 = (size_t)(64*48*4 + 64*68 + 48*4) * 4;  // ~66KB
    cudaFuncSetAttribute(k1, cudaFuncAttributeMaxDynamicSharedMemorySize, (int)smem1);

    void* accPtr = nullptr;
    cudaGetSymbolAddress(&accPtr, g_acc);
    cudaMemsetAsync(accPtr, 0, 152 * sizeof(float));

    k1<<<1024, 256, smem1>>>(x, p, idx, Wq, bq, Wk, bk, Wv, bv, Wp1, bp1);
    k2<<<1024, 256>>>(idx, gp, bpbn, Wp2, bp2);
    k3<<<2048, 256>>>(idx, Wp2, bp2, gw1, bw1bn, Ww1, bw1);
    k4<<<8192, 256>>>(idx, Wp2, bp2, gw2, bw2bn, Ww2, bw2, out);
}